// round 6
// baseline (speedup 1.0000x reference)
#include <cuda_runtime.h>
#include <math.h>
#include <math_constants.h>

#define NB   4
#define NPTS 8192
#define BN   (NB*NPTS)   // 32768
#define D    128
#define KNN  16
#define G    32
#define NCELLS (G*G*G)   // 32768 cells per batch
#define NOCCW  (NCELLS/32)  // 1024 occupancy words per batch

// ---------------- scratch (static device allocations) ----------------
__device__ float4   g_xyzw[BN];        // (-2x,-2y,-2z, |x|^2) per point (orig order)
__device__ float4   g_spts[BN];        // same, sorted by (batch, morton cell)
__device__ int      g_sidx[BN];        // sorted slot -> original local idx
__device__ unsigned g_scell[BN];       // sorted slot -> packed (cx|cy<<5|cz<<10)
__device__ unsigned g_cnt[NB*NCELLS];  // histogram
__device__ unsigned g_off[NB*NCELLS];  // start offsets (batch-local)
__device__ unsigned g_cur[NB*NCELLS];  // scatter cursors -> end offsets after scatter
__device__ unsigned g_occ[NB*NOCCW];   // occupancy bitmap
__device__ unsigned g_bblo[NB*3], g_bbhi[NB*3];  // encoded bbox
__device__ float  g_ksum[BN];          // feat . rowsum(Wk)
__device__ int    g_idx[BN*KNN];       // knn indices (within batch)
__device__ float  g_v[BN*D];           // feat @ Wv + bv
__device__ float  g_hbar[BN*D];        // sum_k attn_k * h_k
__device__ float  g_vbar[BN*D];        // sum_k attn_k * v_k
__device__ float  g_wkrs[D];           // rowsum over out-dim of Wk
__device__ float  g_wp2rs[D];          // rowsum over out-dim of Wp2
__device__ float  g_cvec[D];           // bp2 @ Wo + bo
__device__ float  g_wf[D*D];           // Wp2 @ Wo

// ---------------- helpers ----------------
__device__ __forceinline__ unsigned fenc(float f) {
    unsigned u = __float_as_uint(f);
    return (u & 0x80000000u) ? ~u : (u | 0x80000000u);
}
__device__ __forceinline__ float fdec(unsigned u) {
    return (u & 0x80000000u) ? __uint_as_float(u ^ 0x80000000u) : __uint_as_float(~u);
}
__device__ __forceinline__ unsigned mspread(unsigned x) {
    return (x & 1u) | ((x & 2u) << 2) | ((x & 4u) << 4) | ((x & 8u) << 6) | ((x & 16u) << 8);
}
__device__ __forceinline__ unsigned morton3(int cx, int cy, int cz) {
    return mspread((unsigned)cx) | (mspread((unsigned)cy) << 1) | (mspread((unsigned)cz) << 2);
}
__device__ __forceinline__ int cell1(float x, float lo, float inv) {
    int v = (int)((x - lo) * inv);
    return v < 0 ? 0 : (v > G-1 ? G-1 : v);
}

// ---------------- init ----------------
__global__ void k_zero() {
    int i = blockIdx.x*256 + threadIdx.x;
    if (i < NB*NCELLS) g_cnt[i] = 0;
    if (i < NB*NOCCW)  g_occ[i] = 0;
    if (i < NB*3) { g_bblo[i] = 0xFFFFFFFFu; g_bbhi[i] = 0u; }
}

// ---------------- weight prep ----------------
__global__ void k_weights(const float* __restrict__ Wk, const float* __restrict__ Wp2,
                          const float* __restrict__ bp2, const float* __restrict__ Wo,
                          const float* __restrict__ bo) {
    int i = threadIdx.x;
    float a = 0.f, b = 0.f, c = bo[i];
    for (int j = 0; j < D; ++j) { a += Wk[i*D + j]; b += Wp2[i*D + j]; }
    for (int k = 0; k < D; ++k) c = fmaf(bp2[k], Wo[k*D + i], c);
    g_wkrs[i] = a; g_wp2rs[i] = b; g_cvec[i] = c;
}

__global__ void k_wfused(const float* __restrict__ Wp2, const float* __restrict__ Wo) {
    int d = threadIdx.x & (D-1);
    int i = blockIdx.x*2 + (threadIdx.x >> 7);
    float a = 0.f;
    for (int k = 0; k < D; ++k) a = fmaf(Wp2[i*D + k], Wo[k*D + d], a);
    g_wf[i*D + d] = a;
}

// ---------------- per-point prep: xyzw + ksum ----------------
__global__ void k_prep(const float* __restrict__ xyz, const float* __restrict__ feat) {
    int warp = threadIdx.x >> 5, lane = threadIdx.x & 31;
    int p = blockIdx.x*8 + warp;
    const float* fr = feat + (size_t)p*D;
    float acc = 0.f;
    #pragma unroll
    for (int i = 0; i < 4; ++i) {
        int d = lane + 32*i;
        acc = fmaf(fr[d], g_wkrs[d], acc);
    }
    #pragma unroll
    for (int off = 16; off; off >>= 1) acc += __shfl_xor_sync(0xffffffffu, acc, off);
    if (lane == 0) {
        g_ksum[p] = acc;
        float x = xyz[3*p], y = xyz[3*p+1], z = xyz[3*p+2];
        g_xyzw[p] = make_float4(-2.f*x, -2.f*y, -2.f*z, x*x + y*y + z*z);
    }
}

// ---------------- bbox per batch ----------------
__global__ void k_bbox(const float* __restrict__ xyz) {   // grid (32, NB), block 256
    int b = blockIdx.y;
    __shared__ unsigned slo[3], shi[3];
    if (threadIdx.x < 3) { slo[threadIdx.x] = 0xFFFFFFFFu; shi[threadIdx.x] = 0u; }
    __syncthreads();
    int p = blockIdx.x*256 + threadIdx.x;
    if (p < NPTS) {
        const float* r = xyz + (size_t)(b*NPTS + p)*3;
        #pragma unroll
        for (int a = 0; a < 3; ++a) {
            unsigned e = fenc(r[a]);
            atomicMin(&slo[a], e); atomicMax(&shi[a], e);
        }
    }
    __syncthreads();
    if (threadIdx.x < 3) {
        atomicMin(&g_bblo[b*3 + threadIdx.x], slo[threadIdx.x]);
        atomicMax(&g_bbhi[b*3 + threadIdx.x], shi[threadIdx.x]);
    }
}

// ---------------- histogram ----------------
__global__ void k_hist(const float* __restrict__ xyz) {
    int i = blockIdx.x*256 + threadIdx.x;   // global point
    int b = i >> 13;
    float lox = fdec(g_bblo[b*3]),   loy = fdec(g_bblo[b*3+1]), loz = fdec(g_bblo[b*3+2]);
    float spx = fdec(g_bbhi[b*3])   - lox + 1e-4f;
    float spy = fdec(g_bbhi[b*3+1]) - loy + 1e-4f;
    float spz = fdec(g_bbhi[b*3+2]) - loz + 1e-4f;
    float ivx = (float)G/spx, ivy = (float)G/spy, ivz = (float)G/spz;
    float x = xyz[3*i], y = xyz[3*i+1], z = xyz[3*i+2];
    unsigned m = morton3(cell1(x,lox,ivx), cell1(y,loy,ivy), cell1(z,loz,ivz));
    atomicAdd(&g_cnt[b*NCELLS + m], 1u);
}

// ---------------- exclusive scan per batch ----------------
__global__ void k_scan() {   // grid NB, block 1024
    int b = blockIdx.x;
    int tid = threadIdx.x, lane = tid & 31, wid = tid >> 5;
    __shared__ unsigned ws[32];
    __shared__ unsigned carry_s;
    if (tid == 0) carry_s = 0;
    __syncthreads();
    for (int it = 0; it < NCELLS/1024; ++it) {
        unsigned carry = carry_s;
        int i = b*NCELLS + it*1024 + tid;
        unsigned v = g_cnt[i];
        unsigned s = v;
        #pragma unroll
        for (int off = 1; off < 32; off <<= 1) {
            unsigned n = __shfl_up_sync(0xffffffffu, s, off);
            if (lane >= off) s += n;
        }
        if (lane == 31) ws[wid] = s;
        __syncthreads();
        if (wid == 0) {
            unsigned t = ws[lane];
            #pragma unroll
            for (int off = 1; off < 32; off <<= 1) {
                unsigned n = __shfl_up_sync(0xffffffffu, t, off);
                if (lane >= off) t += n;
            }
            ws[lane] = t;
        }
        __syncthreads();
        unsigned excl = s - v + (wid ? ws[wid-1] : 0u) + carry;
        g_off[i] = excl; g_cur[i] = excl;
        __syncthreads();
        if (tid == 1023) carry_s = excl + v;
        __syncthreads();
    }
}

// ---------------- occupancy bitmap ----------------
__global__ void k_occ() {
    int i = blockIdx.x*256 + threadIdx.x;   // cell global
    if (g_cnt[i]) {
        int b = i / NCELLS; unsigned m = (unsigned)(i % NCELLS);
        atomicOr(&g_occ[b*NOCCW + (m >> 5)], 1u << (m & 31u));
    }
}

// ---------------- scatter into sorted order ----------------
__global__ void k_scatter(const float* __restrict__ xyz) {
    int i = blockIdx.x*256 + threadIdx.x;
    int b = i >> 13;
    float lox = fdec(g_bblo[b*3]),   loy = fdec(g_bblo[b*3+1]), loz = fdec(g_bblo[b*3+2]);
    float spx = fdec(g_bbhi[b*3])   - lox + 1e-4f;
    float spy = fdec(g_bbhi[b*3+1]) - loy + 1e-4f;
    float spz = fdec(g_bbhi[b*3+2]) - loz + 1e-4f;
    float ivx = (float)G/spx, ivy = (float)G/spy, ivz = (float)G/spz;
    float x = xyz[3*i], y = xyz[3*i+1], z = xyz[3*i+2];
    int cx = cell1(x,lox,ivx), cy = cell1(y,loy,ivy), cz = cell1(z,loz,ivz);
    unsigned m = morton3(cx,cy,cz);
    unsigned pos = atomicAdd(&g_cur[b*NCELLS + m], 1u);
    int slot = b*NPTS + (int)pos;
    g_spts[slot]  = g_xyzw[i];
    g_sidx[slot]  = i & (NPTS-1);
    g_scell[slot] = (unsigned)cx | ((unsigned)cy << 5) | ((unsigned)cz << 10);
}

// ---------------- grid kNN: warp = 32 morton-adjacent queries ----------------
__global__ void __launch_bounds__(128) k_knn() {
    __shared__ unsigned socc[NOCCW];
    int w = threadIdx.x >> 5, lane = threadIdx.x & 31;
    int qslot0 = (blockIdx.x*4 + w)*32;
    int b = qslot0 >> 13;
    int bbase = b*NPTS;
    for (int i = threadIdx.x; i < NOCCW; i += 128) socc[i] = g_occ[b*NOCCW + i];
    __syncthreads();

    int slot = qslot0 + lane;
    float4 qc = g_spts[slot];
    float qx = -0.5f*qc.x, qy = -0.5f*qc.y, qz = -0.5f*qc.z, qw = qc.w;
    unsigned qcell = g_scell[slot];
    int cx = qcell & 31, cy = (qcell >> 5) & 31, cz = (qcell >> 10) & 31;

    float lox = fdec(g_bblo[b*3]),   loy = fdec(g_bblo[b*3+1]), loz = fdec(g_bblo[b*3+2]);
    float hx = (fdec(g_bbhi[b*3])   - lox + 1e-4f)/(float)G;
    float hy = (fdec(g_bbhi[b*3+1]) - loy + 1e-4f)/(float)G;
    float hz = (fdec(g_bbhi[b*3+2]) - loz + 1e-4f)/(float)G;
    float hmin = fminf(hx, fminf(hy, hz));

    // warp hull box of query cells
    int bx0 = cx, bx1 = cx, by0 = cy, by1 = cy, bz0 = cz, bz1 = cz;
    #pragma unroll
    for (int off = 16; off; off >>= 1) {
        bx0 = min(bx0, __shfl_xor_sync(0xffffffffu, bx0, off));
        bx1 = max(bx1, __shfl_xor_sync(0xffffffffu, bx1, off));
        by0 = min(by0, __shfl_xor_sync(0xffffffffu, by0, off));
        by1 = max(by1, __shfl_xor_sync(0xffffffffu, by1, off));
        bz0 = min(bz0, __shfl_xor_sync(0xffffffffu, bz0, off));
        bz1 = max(bz1, __shfl_xor_sync(0xffffffffu, bz1, off));
    }

    float kk[KNN]; int ii[KNN];
    #pragma unroll
    for (int s = 0; s < KNN; ++s) { kk[s] = CUDART_INF_F; ii[s] = 0; }
    float bound_d2 = CUDART_INF_F;
    bool  ldone = false;
    float pkey = 0.f; int psl = 0; bool pval = false;

#define KNN_FLUSH() do {                                              \
        float ck = pkey; int ci = g_sidx[bbase + psl];                \
        _Pragma("unroll")                                             \
        for (int s = 0; s < KNN; ++s) {                               \
            bool sw = ck < kk[s];                                     \
            float tk = kk[s]; int ti = ii[s];                         \
            kk[s] = sw ? ck : tk;  ii[s] = sw ? ci : ti;              \
            ck = sw ? tk : ck;     ci = sw ? ti : ci;                 \
        }                                                             \
    } while (0)

    for (int r = 0; r < 2*G; ++r) {
        for (int icz = bz0-r; icz <= bz1+r; ++icz) {
            if ((unsigned)icz >= G) continue;
            bool ze = (icz == bz0-r) || (icz == bz1+r);
            for (int icy = by0-r; icy <= by1+r; ++icy) {
                if ((unsigned)icy >= G) continue;
                bool ye = (icy == by0-r) || (icy == by1+r);
                for (int icx = bx0-r; icx <= bx1+r; ++icx) {
                    if ((unsigned)icx >= G) continue;
                    if (r > 0 && !ze && !ye && !(icx == bx0-r || icx == bx1+r)) continue;
                    unsigned m = morton3(icx, icy, icz);
                    if (!((socc[m >> 5] >> (m & 31u)) & 1u)) continue;
                    // per-lane min distance^2 to this cell
                    float clx = lox + icx*hx, cly = loy + icy*hy, clz = loz + icz*hz;
                    float ddx = fmaxf(fmaxf(clx - qx, qx - (clx + hx)), 0.f);
                    float ddy = fmaxf(fmaxf(cly - qy, qy - (cly + hy)), 0.f);
                    float ddz = fmaxf(fmaxf(clz - qz, qz - (clz + hz)), 0.f);
                    float cd2 = fmaf(ddx, ddx, fmaf(ddy, ddy, ddz*ddz));
                    bool need = (cd2 <= bound_d2 + 1e-4f) && !ldone;
                    if (!__any_sync(0xffffffffu, need)) continue;
                    int s0 = (int)g_off[b*NCELLS + m], s1 = (int)g_cur[b*NCELLS + m];
                    float thr = ldone ? -CUDART_INF_F : kk[KNN-1];
                    for (int j = s0; j < s1; ++j) {
                        float4 c = g_spts[bbase + j];   // broadcast load
                        float key = fmaf(c.x, qx, fmaf(c.y, qy, fmaf(c.z, qz, c.w)));
                        bool hit = key < thr;
                        if (__any_sync(0xffffffffu, hit && pval)) {
                            if (pval) { KNN_FLUSH(); thr = kk[KNN-1]; }
                            pval = false;
                        }
                        if (hit) { pkey = key; psl = j; pval = true; }
                    }
                }
            }
        }
        // ring-end: flush pending, update bound, check termination
        if (__any_sync(0xffffffffu, pval)) {
            if (pval) KNN_FLUSH();
            pval = false;
        }
        bound_d2 = kk[KNN-1] + qw;
        float rr = (float)r * hmin;
        ldone = ldone || (bound_d2 <= rr*rr);
        if (__all_sync(0xffffffffu, ldone)) break;
    }
#undef KNN_FLUSH

    int oq = g_sidx[slot];
    int* op = g_idx + (size_t)(bbase + oq)*KNN;
    #pragma unroll
    for (int s = 0; s < KNN; ++s) op[s] = ii[s];
}

// ---------------- v = feat @ Wv + bv ----------------
__global__ void k_gemm_v(const float* __restrict__ feat, const float* __restrict__ Wv,
                         const float* __restrict__ bv) {
    __shared__ float As[16][132];
    __shared__ float Ws[16][132];
    int m0 = blockIdx.x*128;
    int tx = threadIdx.x & 15, ty = threadIdx.x >> 4;
    float acc[8][8];
    #pragma unroll
    for (int i = 0; i < 8; ++i)
        #pragma unroll
        for (int j = 0; j < 8; ++j) acc[i][j] = 0.f;

    for (int kc = 0; kc < D; kc += 16) {
        __syncthreads();
        { int c = threadIdx.x & 3, r = threadIdx.x >> 2;
          #pragma unroll
          for (int rr = 0; rr < 2; ++rr) {
              int mm = r + rr*64;
              float4 v = *(const float4*)&feat[(size_t)(m0+mm)*D + kc + c*4];
              As[c*4+0][mm] = v.x; As[c*4+1][mm] = v.y;
              As[c*4+2][mm] = v.z; As[c*4+3][mm] = v.w;
          }
        }
        { int k = threadIdx.x >> 5, c4 = threadIdx.x & 31;
          #pragma unroll
          for (int kk = 0; kk < 2; ++kk) {
              float4 v = *(const float4*)&Wv[(size_t)(kc + k + kk*8)*D + c4*4];
              Ws[k + kk*8][c4*4+0] = v.x; Ws[k + kk*8][c4*4+1] = v.y;
              Ws[k + kk*8][c4*4+2] = v.z; Ws[k + kk*8][c4*4+3] = v.w;
          }
        }
        __syncthreads();
        #pragma unroll
        for (int k = 0; k < 16; ++k) {
            float a[8], bb[8];
            #pragma unroll
            for (int i = 0; i < 8; ++i) a[i]  = As[k][ty*8 + i];
            #pragma unroll
            for (int j = 0; j < 8; ++j) bb[j] = Ws[k][tx*8 + j];
            #pragma unroll
            for (int i = 0; i < 8; ++i)
                #pragma unroll
                for (int j = 0; j < 8; ++j) acc[i][j] = fmaf(a[i], bb[j], acc[i][j]);
        }
    }
    #pragma unroll
    for (int i = 0; i < 8; ++i) {
        int m = m0 + ty*8 + i;
        #pragma unroll
        for (int j = 0; j < 8; ++j) acc[i][j] += bv[tx*8 + j];
        *(float4*)&g_v[(size_t)m*D + tx*8]     = make_float4(acc[i][0], acc[i][1], acc[i][2], acc[i][3]);
        *(float4*)&g_v[(size_t)m*D + tx*8 + 4] = make_float4(acc[i][4], acc[i][5], acc[i][6], acc[i][7]);
    }
}

// ---------------- fused attention (warp per point) ----------------
__global__ void k_fuse(const float* __restrict__ xyz, const float* __restrict__ Wp1,
                       const float* __restrict__ bp1) {
    __shared__ float sw0[D], sw1[D], sw2[D], sb1[D], srs[D];
    int tid = threadIdx.x;
    sw0[tid] = Wp1[tid]; sw1[tid] = Wp1[D + tid]; sw2[tid] = Wp1[2*D + tid];
    sb1[tid] = bp1[tid]; srs[tid] = g_wp2rs[tid];
    __syncthreads();

    int warp = tid >> 5, lane = tid & 31;
    int p = blockIdx.x*4 + warp;
    int bbase = p & ~(NPTS-1);

    float w0[4], w1[4], w2[4], b1r[4], rs[4];
    #pragma unroll
    for (int i = 0; i < 4; ++i) {
        int d = lane + 32*i;
        w0[i] = sw0[d]; w1[i] = sw1[d]; w2[i] = sw2[d]; b1r[i] = sb1[d]; rs[i] = srs[d];
    }

    float rx = 0.f, ry = 0.f, rz = 0.f, ks = 0.f; int row = 0;
    if (lane < KNN) {
        int nb = g_idx[(size_t)p*KNN + lane];
        row = bbase + nb;
        float qx = xyz[3*p], qy = xyz[3*p+1], qz = xyz[3*p+2];
        rx = qx - xyz[3*row]; ry = qy - xyz[3*row+1]; rz = qz - xyz[3*row+2];
        ks = g_ksum[row];
    }

    float mysc = -CUDART_INF_F;
    #pragma unroll
    for (int k = 0; k < KNN; ++k) {
        float bx = __shfl_sync(0xffffffffu, rx, k);
        float by = __shfl_sync(0xffffffffu, ry, k);
        float bz = __shfl_sync(0xffffffffu, rz, k);
        float part = 0.f;
        #pragma unroll
        for (int i = 0; i < 4; ++i) {
            float h = fmaf(bx, w0[i], fmaf(by, w1[i], fmaf(bz, w2[i], b1r[i])));
            h = fmaxf(h, 0.f);
            part = fmaf(h, rs[i], part);
        }
        #pragma unroll
        for (int off = 16; off; off >>= 1) part += __shfl_xor_sync(0xffffffffu, part, off);
        if (lane == k) mysc = part - ks;
    }
    float mx = mysc;
    #pragma unroll
    for (int off = 16; off; off >>= 1) mx = fmaxf(mx, __shfl_xor_sync(0xffffffffu, mx, off));
    float e = (lane < KNN) ? __expf(mysc - mx) : 0.f;
    float ssum = e;
    #pragma unroll
    for (int off = 16; off; off >>= 1) ssum += __shfl_xor_sync(0xffffffffu, ssum, off);
    float attn = e / ssum;

    float hb[4] = {0,0,0,0}, vb[4] = {0,0,0,0};
    #pragma unroll
    for (int k = 0; k < KNN; ++k) {
        float a  = __shfl_sync(0xffffffffu, attn, k);
        float bx = __shfl_sync(0xffffffffu, rx, k);
        float by = __shfl_sync(0xffffffffu, ry, k);
        float bz = __shfl_sync(0xffffffffu, rz, k);
        int   r  = __shfl_sync(0xffffffffu, row, k);
        const float* vr = g_v + (size_t)r*D;
        #pragma unroll
        for (int i = 0; i < 4; ++i) {
            int d = lane + 32*i;
            float h = fmaf(bx, w0[i], fmaf(by, w1[i], fmaf(bz, w2[i], b1r[i])));
            h = fmaxf(h, 0.f);
            hb[i] = fmaf(a, h, hb[i]);
            vb[i] = fmaf(a, vr[d], vb[i]);
        }
    }
    #pragma unroll
    for (int i = 0; i < 4; ++i) {
        int d = lane + 32*i;
        g_hbar[(size_t)p*D + d] = hb[i];
        g_vbar[(size_t)p*D + d] = vb[i];
    }
}

// ---------------- out = feat + gamma*(vbar@Wo + hbar@Wf + cvec) ----------------
__global__ void k_out(const float* __restrict__ feat, const float* __restrict__ Wo,
                      const float* __restrict__ gamma, float* __restrict__ out) {
    __shared__ float As[16][132];
    __shared__ float Ws[16][132];
    int m0 = blockIdx.x*128;
    int tx = threadIdx.x & 15, ty = threadIdx.x >> 4;
    float acc[8][8];
    #pragma unroll
    for (int i = 0; i < 8; ++i)
        #pragma unroll
        for (int j = 0; j < 8; ++j) acc[i][j] = 0.f;

    for (int ph = 0; ph < 2; ++ph) {
        const float* A = ph ? g_hbar : g_vbar;
        const float* W = ph ? g_wf   : Wo;
        for (int kc = 0; kc < D; kc += 16) {
            __syncthreads();
            { int c = threadIdx.x & 3, r = threadIdx.x >> 2;
              #pragma unroll
              for (int rr = 0; rr < 2; ++rr) {
                  int mm = r + rr*64;
                  float4 v = *(const float4*)&A[(size_t)(m0+mm)*D + kc + c*4];
                  As[c*4+0][mm] = v.x; As[c*4+1][mm] = v.y;
                  As[c*4+2][mm] = v.z; As[c*4+3][mm] = v.w;
              }
            }
            { int k = threadIdx.x >> 5, c4 = threadIdx.x & 31;
              #pragma unroll
              for (int kk = 0; kk < 2; ++kk) {
                  float4 v = *(const float4*)&W[(size_t)(kc + k + kk*8)*D + c4*4];
                  Ws[k + kk*8][c4*4+0] = v.x; Ws[k + kk*8][c4*4+1] = v.y;
                  Ws[k + kk*8][c4*4+2] = v.z; Ws[k + kk*8][c4*4+3] = v.w;
              }
            }
            __syncthreads();
            #pragma unroll
            for (int k = 0; k < 16; ++k) {
                float a[8], bb[8];
                #pragma unroll
                for (int i = 0; i < 8; ++i) a[i]  = As[k][ty*8 + i];
                #pragma unroll
                for (int j = 0; j < 8; ++j) bb[j] = Ws[k][tx*8 + j];
                #pragma unroll
                for (int i = 0; i < 8; ++i)
                    #pragma unroll
                    for (int j = 0; j < 8; ++j) acc[i][j] = fmaf(a[i], bb[j], acc[i][j]);
            }
        }
    }
    float g = *gamma;
    float cv[8];
    #pragma unroll
    for (int j = 0; j < 8; ++j) cv[j] = g_cvec[tx*8 + j];
    #pragma unroll
    for (int i = 0; i < 8; ++i) {
        int m = m0 + ty*8 + i;
        float4 f0 = *(const float4*)&feat[(size_t)m*D + tx*8];
        float4 f1 = *(const float4*)&feat[(size_t)m*D + tx*8 + 4];
        float o0 = f0.x + g*(acc[i][0] + cv[0]);
        float o1 = f0.y + g*(acc[i][1] + cv[1]);
        float o2 = f0.z + g*(acc[i][2] + cv[2]);
        float o3 = f0.w + g*(acc[i][3] + cv[3]);
        float o4 = f1.x + g*(acc[i][4] + cv[4]);
        float o5 = f1.y + g*(acc[i][5] + cv[5]);
        float o6 = f1.z + g*(acc[i][6] + cv[6]);
        float o7 = f1.w + g*(acc[i][7] + cv[7]);
        *(float4*)&out[(size_t)m*D + tx*8]     = make_float4(o0, o1, o2, o3);
        *(float4*)&out[(size_t)m*D + tx*8 + 4] = make_float4(o4, o5, o6, o7);
    }
}

// ---------------- launch ----------------
extern "C" void kernel_launch(void* const* d_in, const int* in_sizes, int n_in,
                              void* d_out, int out_size) {
    const float* xyz  = (const float*)d_in[0];
    const float* feat = (const float*)d_in[1];
    // d_in[2]=Wq, d_in[3]=bq, d_in[5]=bk : mathematically cancel in softmax, unused
    const float* Wk   = (const float*)d_in[4];
    const float* Wv   = (const float*)d_in[6];
    const float* bv   = (const float*)d_in[7];
    const float* Wp1  = (const float*)d_in[8];
    const float* bp1  = (const float*)d_in[9];
    const float* Wp2  = (const float*)d_in[10];
    const float* bp2  = (const float*)d_in[11];
    const float* Wo   = (const float*)d_in[12];
    const float* bo   = (const float*)d_in[13];
    const float* gmm  = (const float*)d_in[14];
    float* out = (float*)d_out;

    k_zero<<<(NB*NCELLS + 255)/256, 256>>>();
    k_weights<<<1, 128>>>(Wk, Wp2, bp2, Wo, bo);
    k_wfused<<<64, 256>>>(Wp2, Wo);
    k_prep<<<BN/8, 256>>>(xyz, feat);
    k_bbox<<<dim3(32, NB), 256>>>(xyz);
    k_hist<<<BN/256, 256>>>(xyz);
    k_scan<<<NB, 1024>>>();
    k_occ<<<(NB*NCELLS)/256, 256>>>();
    k_scatter<<<BN/256, 256>>>(xyz);
    k_knn<<<BN/128, 128>>>();
    k_gemm_v<<<BN/128, 256>>>(feat, Wv, bv);
    k_fuse<<<BN/4, 128>>>(xyz, Wp1, bp1);
    k_out<<<BN/128, 256>>>(feat, Wo, gmm, out);
}

// round 7
// speedup vs baseline: 9.0259x; 9.0259x over previous
#include <cuda_runtime.h>
#include <math.h>
#include <math_constants.h>

#define NB   4
#define NPTS 8192
#define BN   (NB*NPTS)   // 32768
#define D    128
#define KNN  16
#define NBINS 256

// ---------------- scratch (static device allocations) ----------------
__device__ float4   g_xyzw[BN];        // (-2x,-2y,-2z, |x|^2) per point (orig order)
__device__ float4   g_spts[BN];        // same, sorted by (batch, x-bin)
__device__ int      g_sidx[BN];        // sorted slot -> original local idx
__device__ unsigned char g_sbin[BN];   // sorted slot -> bin
__device__ unsigned g_cnt[NB*NBINS];   // histogram
__device__ unsigned g_off[NB*NBINS];   // bin start offsets (batch-local)
__device__ unsigned g_cur[NB*NBINS];   // scatter cursors -> bin end after scatter
__device__ unsigned g_bblo[NB], g_bbhi[NB];      // encoded x-bbox
__device__ float  g_ksum[BN];          // feat . rowsum(Wk)
__device__ int    g_idx[BN*KNN];       // knn indices (within batch)
__device__ float  g_v[BN*D];           // feat @ Wv + bv
__device__ float  g_hbar[BN*D];        // sum_k attn_k * h_k
__device__ float  g_vbar[BN*D];        // sum_k attn_k * v_k
__device__ float  g_wkrs[D];           // rowsum over out-dim of Wk
__device__ float  g_wp2rs[D];          // rowsum over out-dim of Wp2
__device__ float  g_cvec[D];           // bp2 @ Wo + bo
__device__ float  g_wf[D*D];           // Wp2 @ Wo

// ---------------- helpers ----------------
__device__ __forceinline__ unsigned fenc(float f) {
    unsigned u = __float_as_uint(f);
    return (u & 0x80000000u) ? ~u : (u | 0x80000000u);
}
__device__ __forceinline__ float fdec(unsigned u) {
    return (u & 0x80000000u) ? __uint_as_float(u ^ 0x80000000u) : __uint_as_float(~u);
}
__device__ __forceinline__ int xbin(float x, float lo, float inv) {
    int v = (int)((x - lo) * inv);
    return v < 0 ? 0 : (v > NBINS-1 ? NBINS-1 : v);
}

// ---------------- init ----------------
__global__ void k_zero() {   // 1 block, 1024 threads
    int i = threadIdx.x;
    g_cnt[i] = 0;
    if (i < NB) { g_bblo[i] = 0xFFFFFFFFu; g_bbhi[i] = 0u; }
}

// ---------------- weight prep ----------------
__global__ void k_weights(const float* __restrict__ Wk, const float* __restrict__ Wp2,
                          const float* __restrict__ bp2, const float* __restrict__ Wo,
                          const float* __restrict__ bo) {
    int i = threadIdx.x;
    float a = 0.f, b = 0.f, c = bo[i];
    for (int j = 0; j < D; ++j) { a += Wk[i*D + j]; b += Wp2[i*D + j]; }
    for (int k = 0; k < D; ++k) c = fmaf(bp2[k], Wo[k*D + i], c);
    g_wkrs[i] = a; g_wp2rs[i] = b; g_cvec[i] = c;
}

__global__ void k_wfused(const float* __restrict__ Wp2, const float* __restrict__ Wo) {
    int d = threadIdx.x & (D-1);
    int i = blockIdx.x*2 + (threadIdx.x >> 7);
    float a = 0.f;
    for (int k = 0; k < D; ++k) a = fmaf(Wp2[i*D + k], Wo[k*D + d], a);
    g_wf[i*D + d] = a;
}

// ---------------- per-point prep: xyzw + ksum + x-bbox ----------------
__global__ void k_prep(const float* __restrict__ xyz, const float* __restrict__ feat) {
    __shared__ unsigned slo, shi;
    if (threadIdx.x == 0) { slo = 0xFFFFFFFFu; shi = 0u; }
    __syncthreads();
    int warp = threadIdx.x >> 5, lane = threadIdx.x & 31;
    int p = blockIdx.x*8 + warp;
    const float* fr = feat + (size_t)p*D;
    float acc = 0.f;
    #pragma unroll
    for (int i = 0; i < 4; ++i) {
        int d = lane + 32*i;
        acc = fmaf(fr[d], g_wkrs[d], acc);
    }
    #pragma unroll
    for (int off = 16; off; off >>= 1) acc += __shfl_xor_sync(0xffffffffu, acc, off);
    if (lane == 0) {
        g_ksum[p] = acc;
        float x = xyz[3*p], y = xyz[3*p+1], z = xyz[3*p+2];
        g_xyzw[p] = make_float4(-2.f*x, -2.f*y, -2.f*z, x*x + y*y + z*z);
        unsigned e = fenc(x);
        atomicMin(&slo, e); atomicMax(&shi, e);
    }
    __syncthreads();
    if (threadIdx.x == 0) {
        int b = (blockIdx.x*8) >> 13;   // all 8 points of a block share a batch
        atomicMin(&g_bblo[b], slo); atomicMax(&g_bbhi[b], shi);
    }
}

// ---------------- histogram over x-bins ----------------
__global__ void k_hist(const float* __restrict__ xyz) {
    int i = blockIdx.x*256 + threadIdx.x;
    int b = i >> 13;
    float lo = fdec(g_bblo[b]);
    float inv = (float)NBINS / (fdec(g_bbhi[b]) - lo + 1e-4f);
    atomicAdd(&g_cnt[b*NBINS + xbin(xyz[3*i], lo, inv)], 1u);
}

// ---------------- exclusive scan (256 bins per batch) ----------------
__global__ void k_scan() {   // grid NB, block 256
    int b = blockIdx.x, tid = threadIdx.x, lane = tid & 31, wid = tid >> 5;
    __shared__ unsigned ws[8];
    unsigned v = g_cnt[b*NBINS + tid], s = v;
    #pragma unroll
    for (int off = 1; off < 32; off <<= 1) {
        unsigned n = __shfl_up_sync(0xffffffffu, s, off);
        if (lane >= off) s += n;
    }
    if (lane == 31) ws[wid] = s;
    __syncthreads();
    if (wid == 0 && lane < 8) {
        unsigned t = ws[lane];
        #pragma unroll
        for (int off = 1; off < 8; off <<= 1) {
            unsigned n = __shfl_up_sync(0xFFu, t, off, 8);
            if (lane >= off) t += n;
        }
        ws[lane] = t;
    }
    __syncthreads();
    unsigned excl = s - v + (wid ? ws[wid-1] : 0u);
    g_off[b*NBINS + tid] = excl;
    g_cur[b*NBINS + tid] = excl;
}

// ---------------- scatter into sorted order ----------------
__global__ void k_scatter(const float* __restrict__ xyz) {
    int i = blockIdx.x*256 + threadIdx.x;
    int b = i >> 13;
    float lo = fdec(g_bblo[b]);
    float inv = (float)NBINS / (fdec(g_bbhi[b]) - lo + 1e-4f);
    int bin = xbin(xyz[3*i], lo, inv);
    unsigned pos = atomicAdd(&g_cur[b*NBINS + bin], 1u);
    int slot = b*NPTS + (int)pos;
    g_spts[slot] = g_xyzw[i];
    g_sidx[slot] = i & (NPTS-1);
    g_sbin[slot] = (unsigned char)bin;
}

// ---------------- kNN: x-sorted outward scan with exact dx bound ----------------
__global__ void __launch_bounds__(128) k_knn() {
    int w = threadIdx.x >> 5, lane = threadIdx.x & 31;
    int slot = (blockIdx.x*4 + w)*32 + lane;
    int b = slot >> 13, bbase = b*NPTS;
    float4 qc = g_spts[slot];
    float qx = -0.5f*qc.x, qy = -0.5f*qc.y, qz = -0.5f*qc.z, qw = qc.w;

    float lo = fdec(g_bblo[b]);
    float h = (fdec(g_bbhi[b]) - lo + 1e-4f) / (float)NBINS;
    int bc = __shfl_sync(0xffffffffu, (int)g_sbin[slot], 16);  // warp-center bin

    float kk[KNN]; int ii[KNN];
    #pragma unroll
    for (int s = 0; s < KNN; ++s) { kk[s] = CUDART_INF_F; ii[s] = 0; }
    float pkey = 0.f; int psl = 0; bool pval = false;

#define KNN_FLUSH() do {                                              \
        float ck = pkey; int ci = g_sidx[bbase + psl];                \
        _Pragma("unroll")                                             \
        for (int s = 0; s < KNN; ++s) {                               \
            bool sw = ck < kk[s];                                     \
            float tk = kk[s]; int ti = ii[s];                         \
            kk[s] = sw ? ck : tk;  ii[s] = sw ? ci : ti;              \
            ck = sw ? tk : ck;     ci = sw ? ti : ci;                 \
        }                                                             \
    } while (0)

#define SCAN_BIN(J) do {                                              \
        int s0 = (int)g_off[b*NBINS + (J)], s1 = (int)g_cur[b*NBINS + (J)]; \
        float thr = kk[KNN-1];                                        \
        for (int j2 = s0; j2 < s1; ++j2) {                            \
            float4 c = g_spts[bbase + j2];                            \
            float key = fmaf(c.x, qx, fmaf(c.y, qy, fmaf(c.z, qz, c.w))); \
            bool hit = key < thr;                                     \
            if (__any_sync(0xffffffffu, hit && pval)) {               \
                if (pval) { KNN_FLUSH(); thr = kk[KNN-1]; }           \
                pval = false;                                         \
            }                                                         \
            if (hit) { pkey = key; psl = j2; pval = true; }           \
        }                                                             \
    } while (0)

    SCAN_BIN(bc);
    bool rdone = false, ldone = false;
    for (int s = 1; s < NBINS && !(rdone && ldone); ++s) {
        float d2 = kk[KNN-1] + qw;      // current (conservative) dist^2 bound
        if (!rdone) {
            int j = bc + s;
            if (j >= NBINS) rdone = true;
            else {
                float dx = lo + (float)j*h - qx;       // near (left) edge of right bin
                bool sat = (dx > 0.f) && (dx*dx >= d2);
                if (__all_sync(0xffffffffu, sat)) rdone = true;
                else SCAN_BIN(j);
            }
        }
        if (!ldone) {
            int j = bc - s;
            if (j < 0) ldone = true;
            else {
                float dx = qx - (lo + (float)(j+1)*h); // near (right) edge of left bin
                bool sat = (dx > 0.f) && (dx*dx >= d2);
                if (__all_sync(0xffffffffu, sat)) ldone = true;
                else SCAN_BIN(j);
            }
        }
    }
    if (__any_sync(0xffffffffu, pval)) {
        if (pval) KNN_FLUSH();
    }
#undef SCAN_BIN
#undef KNN_FLUSH

    int oq = g_sidx[slot];
    int* op = g_idx + (size_t)(bbase + oq)*KNN;
    #pragma unroll
    for (int s = 0; s < KNN; ++s) op[s] = ii[s];
}

// ---------------- v = feat @ Wv + bv ----------------
__global__ void k_gemm_v(const float* __restrict__ feat, const float* __restrict__ Wv,
                         const float* __restrict__ bv) {
    __shared__ float As[16][132];
    __shared__ float Ws[16][132];
    int m0 = blockIdx.x*128;
    int tx = threadIdx.x & 15, ty = threadIdx.x >> 4;
    float acc[8][8];
    #pragma unroll
    for (int i = 0; i < 8; ++i)
        #pragma unroll
        for (int j = 0; j < 8; ++j) acc[i][j] = 0.f;

    for (int kc = 0; kc < D; kc += 16) {
        __syncthreads();
        { int c = threadIdx.x & 3, r = threadIdx.x >> 2;
          #pragma unroll
          for (int rr = 0; rr < 2; ++rr) {
              int mm = r + rr*64;
              float4 v = *(const float4*)&feat[(size_t)(m0+mm)*D + kc + c*4];
              As[c*4+0][mm] = v.x; As[c*4+1][mm] = v.y;
              As[c*4+2][mm] = v.z; As[c*4+3][mm] = v.w;
          }
        }
        { int k = threadIdx.x >> 5, c4 = threadIdx.x & 31;
          #pragma unroll
          for (int kk = 0; kk < 2; ++kk) {
              float4 v = *(const float4*)&Wv[(size_t)(kc + k + kk*8)*D + c4*4];
              Ws[k + kk*8][c4*4+0] = v.x; Ws[k + kk*8][c4*4+1] = v.y;
              Ws[k + kk*8][c4*4+2] = v.z; Ws[k + kk*8][c4*4+3] = v.w;
          }
        }
        __syncthreads();
        #pragma unroll
        for (int k = 0; k < 16; ++k) {
            float a[8], bb[8];
            #pragma unroll
            for (int i = 0; i < 8; ++i) a[i]  = As[k][ty*8 + i];
            #pragma unroll
            for (int j = 0; j < 8; ++j) bb[j] = Ws[k][tx*8 + j];
            #pragma unroll
            for (int i = 0; i < 8; ++i)
                #pragma unroll
                for (int j = 0; j < 8; ++j) acc[i][j] = fmaf(a[i], bb[j], acc[i][j]);
        }
    }
    #pragma unroll
    for (int i = 0; i < 8; ++i) {
        int m = m0 + ty*8 + i;
        #pragma unroll
        for (int j = 0; j < 8; ++j) acc[i][j] += bv[tx*8 + j];
        *(float4*)&g_v[(size_t)m*D + tx*8]     = make_float4(acc[i][0], acc[i][1], acc[i][2], acc[i][3]);
        *(float4*)&g_v[(size_t)m*D + tx*8 + 4] = make_float4(acc[i][4], acc[i][5], acc[i][6], acc[i][7]);
    }
}

// ---------------- fused attention (warp per point) ----------------
__global__ void k_fuse(const float* __restrict__ xyz, const float* __restrict__ Wp1,
                       const float* __restrict__ bp1) {
    __shared__ float sw0[D], sw1[D], sw2[D], sb1[D], srs[D];
    int tid = threadIdx.x;
    sw0[tid] = Wp1[tid]; sw1[tid] = Wp1[D + tid]; sw2[tid] = Wp1[2*D + tid];
    sb1[tid] = bp1[tid]; srs[tid] = g_wp2rs[tid];
    __syncthreads();

    int warp = tid >> 5, lane = tid & 31;
    int p = blockIdx.x*4 + warp;
    int bbase = p & ~(NPTS-1);

    float w0[4], w1[4], w2[4], b1r[4], rs[4];
    #pragma unroll
    for (int i = 0; i < 4; ++i) {
        int d = lane + 32*i;
        w0[i] = sw0[d]; w1[i] = sw1[d]; w2[i] = sw2[d]; b1r[i] = sb1[d]; rs[i] = srs[d];
    }

    float rx = 0.f, ry = 0.f, rz = 0.f, ks = 0.f; int row = 0;
    if (lane < KNN) {
        int nb = g_idx[(size_t)p*KNN + lane];
        row = bbase + nb;
        float qx = xyz[3*p], qy = xyz[3*p+1], qz = xyz[3*p+2];
        rx = qx - xyz[3*row]; ry = qy - xyz[3*row+1]; rz = qz - xyz[3*row+2];
        ks = g_ksum[row];
    }

    float mysc = -CUDART_INF_F;
    #pragma unroll
    for (int k = 0; k < KNN; ++k) {
        float bx = __shfl_sync(0xffffffffu, rx, k);
        float by = __shfl_sync(0xffffffffu, ry, k);
        float bz = __shfl_sync(0xffffffffu, rz, k);
        float part = 0.f;
        #pragma unroll
        for (int i = 0; i < 4; ++i) {
            float h = fmaf(bx, w0[i], fmaf(by, w1[i], fmaf(bz, w2[i], b1r[i])));
            h = fmaxf(h, 0.f);
            part = fmaf(h, rs[i], part);
        }
        #pragma unroll
        for (int off = 16; off; off >>= 1) part += __shfl_xor_sync(0xffffffffu, part, off);
        if (lane == k) mysc = part - ks;
    }
    float mx = mysc;
    #pragma unroll
    for (int off = 16; off; off >>= 1) mx = fmaxf(mx, __shfl_xor_sync(0xffffffffu, mx, off));
    float e = (lane < KNN) ? __expf(mysc - mx) : 0.f;
    float ssum = e;
    #pragma unroll
    for (int off = 16; off; off >>= 1) ssum += __shfl_xor_sync(0xffffffffu, ssum, off);
    float attn = e / ssum;

    float hb[4] = {0,0,0,0}, vb[4] = {0,0,0,0};
    #pragma unroll
    for (int k = 0; k < KNN; ++k) {
        float a  = __shfl_sync(0xffffffffu, attn, k);
        float bx = __shfl_sync(0xffffffffu, rx, k);
        float by = __shfl_sync(0xffffffffu, ry, k);
        float bz = __shfl_sync(0xffffffffu, rz, k);
        int   r  = __shfl_sync(0xffffffffu, row, k);
        const float* vr = g_v + (size_t)r*D;
        #pragma unroll
        for (int i = 0; i < 4; ++i) {
            int d = lane + 32*i;
            float h = fmaf(bx, w0[i], fmaf(by, w1[i], fmaf(bz, w2[i], b1r[i])));
            h = fmaxf(h, 0.f);
            hb[i] = fmaf(a, h, hb[i]);
            vb[i] = fmaf(a, vr[d], vb[i]);
        }
    }
    #pragma unroll
    for (int i = 0; i < 4; ++i) {
        int d = lane + 32*i;
        g_hbar[(size_t)p*D + d] = hb[i];
        g_vbar[(size_t)p*D + d] = vb[i];
    }
}

// ---------------- out = feat + gamma*(vbar@Wo + hbar@Wf + cvec) ----------------
__global__ void k_out(const float* __restrict__ feat, const float* __restrict__ Wo,
                      const float* __restrict__ gamma, float* __restrict__ out) {
    __shared__ float As[16][132];
    __shared__ float Ws[16][132];
    int m0 = blockIdx.x*128;
    int tx = threadIdx.x & 15, ty = threadIdx.x >> 4;
    float acc[8][8];
    #pragma unroll
    for (int i = 0; i < 8; ++i)
        #pragma unroll
        for (int j = 0; j < 8; ++j) acc[i][j] = 0.f;

    for (int ph = 0; ph < 2; ++ph) {
        const float* A = ph ? g_hbar : g_vbar;
        const float* W = ph ? g_wf   : Wo;
        for (int kc = 0; kc < D; kc += 16) {
            __syncthreads();
            { int c = threadIdx.x & 3, r = threadIdx.x >> 2;
              #pragma unroll
              for (int rr = 0; rr < 2; ++rr) {
                  int mm = r + rr*64;
                  float4 v = *(const float4*)&A[(size_t)(m0+mm)*D + kc + c*4];
                  As[c*4+0][mm] = v.x; As[c*4+1][mm] = v.y;
                  As[c*4+2][mm] = v.z; As[c*4+3][mm] = v.w;
              }
            }
            { int k = threadIdx.x >> 5, c4 = threadIdx.x & 31;
              #pragma unroll
              for (int kk = 0; kk < 2; ++kk) {
                  float4 v = *(const float4*)&W[(size_t)(kc + k + kk*8)*D + c4*4];
                  Ws[k + kk*8][c4*4+0] = v.x; Ws[k + kk*8][c4*4+1] = v.y;
                  Ws[k + kk*8][c4*4+2] = v.z; Ws[k + kk*8][c4*4+3] = v.w;
              }
            }
            __syncthreads();
            #pragma unroll
            for (int k = 0; k < 16; ++k) {
                float a[8], bb[8];
                #pragma unroll
                for (int i = 0; i < 8; ++i) a[i]  = As[k][ty*8 + i];
                #pragma unroll
                for (int j = 0; j < 8; ++j) bb[j] = Ws[k][tx*8 + j];
                #pragma unroll
                for (int i = 0; i < 8; ++i)
                    #pragma unroll
                    for (int j = 0; j < 8; ++j) acc[i][j] = fmaf(a[i], bb[j], acc[i][j]);
            }
        }
    }
    float g = *gamma;
    float cv[8];
    #pragma unroll
    for (int j = 0; j < 8; ++j) cv[j] = g_cvec[tx*8 + j];
    #pragma unroll
    for (int i = 0; i < 8; ++i) {
        int m = m0 + ty*8 + i;
        float4 f0 = *(const float4*)&feat[(size_t)m*D + tx*8];
        float4 f1 = *(const float4*)&feat[(size_t)m*D + tx*8 + 4];
        float o0 = f0.x + g*(acc[i][0] + cv[0]);
        float o1 = f0.y + g*(acc[i][1] + cv[1]);
        float o2 = f0.z + g*(acc[i][2] + cv[2]);
        float o3 = f0.w + g*(acc[i][3] + cv[3]);
        float o4 = f1.x + g*(acc[i][4] + cv[4]);
        float o5 = f1.y + g*(acc[i][5] + cv[5]);
        float o6 = f1.z + g*(acc[i][6] + cv[6]);
        float o7 = f1.w + g*(acc[i][7] + cv[7]);
        *(float4*)&out[(size_t)m*D + tx*8]     = make_float4(o0, o1, o2, o3);
        *(float4*)&out[(size_t)m*D + tx*8 + 4] = make_float4(o4, o5, o6, o7);
    }
}

// ---------------- launch ----------------
extern "C" void kernel_launch(void* const* d_in, const int* in_sizes, int n_in,
                              void* d_out, int out_size) {
    const float* xyz  = (const float*)d_in[0];
    const float* feat = (const float*)d_in[1];
    // d_in[2]=Wq, d_in[3]=bq, d_in[5]=bk : mathematically cancel in softmax, unused
    const float* Wk   = (const float*)d_in[4];
    const float* Wv   = (const float*)d_in[6];
    const float* bv   = (const float*)d_in[7];
    const float* Wp1  = (const float*)d_in[8];
    const float* bp1  = (const float*)d_in[9];
    const float* Wp2  = (const float*)d_in[10];
    const float* bp2  = (const float*)d_in[11];
    const float* Wo   = (const float*)d_in[12];
    const float* bo   = (const float*)d_in[13];
    const float* gmm  = (const float*)d_in[14];
    float* out = (float*)d_out;

    k_zero<<<1, 1024>>>();
    k_weights<<<1, 128>>>(Wk, Wp2, bp2, Wo, bo);
    k_wfused<<<64, 256>>>(Wp2, Wo);
    k_prep<<<BN/8, 256>>>(xyz, feat);
    k_hist<<<BN/256, 256>>>(xyz);
    k_scan<<<NB, 256>>>();
    k_scatter<<<BN/256, 256>>>(xyz);
    k_knn<<<BN/128, 128>>>();
    k_gemm_v<<<BN/128, 256>>>(feat, Wv, bv);
    k_fuse<<<BN/4, 128>>>(xyz, Wp1, bp1);
    k_out<<<BN/128, 256>>>(feat, Wo, gmm, out);
}

// round 8
// speedup vs baseline: 18.2117x; 2.0177x over previous
#include <cuda_runtime.h>
#include <math.h>
#include <math_constants.h>

#define NB   4
#define NPTS 8192
#define BN   (NB*NPTS)   // 32768
#define D    128
#define KNN  16
#define NBINS 256
#define TPW  128         // tile slots per warp

// ---------------- scratch (static device allocations) ----------------
__device__ float4   g_xyzw[BN];        // (-2x,-2y,-2z, |x|^2) per point (orig order)
__device__ float4   g_spts[BN];        // same, sorted by (batch, x-bin)
__device__ int      g_sidx[BN];        // sorted slot -> original local idx
__device__ unsigned char g_sbin[BN];   // sorted slot -> bin
__device__ unsigned g_cnt[NB*NBINS];   // histogram
__device__ unsigned g_off[NB*NBINS];   // bin start offsets (batch-local)
__device__ unsigned g_cur[NB*NBINS];   // scatter cursors
__device__ unsigned g_bblo[NB], g_bbhi[NB];      // encoded x-bbox
__device__ float  g_ksum[BN];          // feat . rowsum(Wk)
__device__ int    g_idx[BN*KNN];       // knn indices (within batch)
__device__ float  g_v[BN*D];           // feat @ Wv + bv
__device__ float  g_hbar[BN*D];        // sum_k attn_k * h_k
__device__ float  g_vbar[BN*D];        // sum_k attn_k * v_k
__device__ float  g_wkrs[D];           // rowsum over out-dim of Wk
__device__ float  g_wp2rs[D];          // rowsum over out-dim of Wp2
__device__ float  g_cvec[D];           // bp2 @ Wo + bo
__device__ float  g_wf[D*D];           // Wp2 @ Wo

// ---------------- helpers ----------------
__device__ __forceinline__ unsigned fenc(float f) {
    unsigned u = __float_as_uint(f);
    return (u & 0x80000000u) ? ~u : (u | 0x80000000u);
}
__device__ __forceinline__ float fdec(unsigned u) {
    return (u & 0x80000000u) ? __uint_as_float(u ^ 0x80000000u) : __uint_as_float(~u);
}
__device__ __forceinline__ int xbin(float x, float lo, float inv) {
    int v = (int)((x - lo) * inv);
    return v < 0 ? 0 : (v > NBINS-1 ? NBINS-1 : v);
}

// ---------------- init ----------------
__global__ void k_zero() {   // 1 block, 1024 threads
    int i = threadIdx.x;
    g_cnt[i] = 0;
    if (i < NB) { g_bblo[i] = 0xFFFFFFFFu; g_bbhi[i] = 0u; }
}

// ---------------- weight prep ----------------
__global__ void k_weights(const float* __restrict__ Wk, const float* __restrict__ Wp2,
                          const float* __restrict__ bp2, const float* __restrict__ Wo,
                          const float* __restrict__ bo) {
    int i = threadIdx.x;
    float a = 0.f, b = 0.f, c = bo[i];
    for (int j = 0; j < D; ++j) { a += Wk[i*D + j]; b += Wp2[i*D + j]; }
    for (int k = 0; k < D; ++k) c = fmaf(bp2[k], Wo[k*D + i], c);
    g_wkrs[i] = a; g_wp2rs[i] = b; g_cvec[i] = c;
}

__global__ void k_wfused(const float* __restrict__ Wp2, const float* __restrict__ Wo) {
    int d = threadIdx.x & (D-1);
    int i = blockIdx.x*2 + (threadIdx.x >> 7);
    float a = 0.f;
    for (int k = 0; k < D; ++k) a = fmaf(Wp2[i*D + k], Wo[k*D + d], a);
    g_wf[i*D + d] = a;
}

// ---------------- per-point prep: xyzw + ksum + x-bbox ----------------
__global__ void k_prep(const float* __restrict__ xyz, const float* __restrict__ feat) {
    __shared__ unsigned slo, shi;
    if (threadIdx.x == 0) { slo = 0xFFFFFFFFu; shi = 0u; }
    __syncthreads();
    int warp = threadIdx.x >> 5, lane = threadIdx.x & 31;
    int p = blockIdx.x*8 + warp;
    const float* fr = feat + (size_t)p*D;
    float acc = 0.f;
    #pragma unroll
    for (int i = 0; i < 4; ++i) {
        int d = lane + 32*i;
        acc = fmaf(fr[d], g_wkrs[d], acc);
    }
    #pragma unroll
    for (int off = 16; off; off >>= 1) acc += __shfl_xor_sync(0xffffffffu, acc, off);
    if (lane == 0) {
        g_ksum[p] = acc;
        float x = xyz[3*p], y = xyz[3*p+1], z = xyz[3*p+2];
        g_xyzw[p] = make_float4(-2.f*x, -2.f*y, -2.f*z, x*x + y*y + z*z);
        unsigned e = fenc(x);
        atomicMin(&slo, e); atomicMax(&shi, e);
    }
    __syncthreads();
    if (threadIdx.x == 0) {
        int b = (blockIdx.x*8) >> 13;
        atomicMin(&g_bblo[b], slo); atomicMax(&g_bbhi[b], shi);
    }
}

// ---------------- histogram over x-bins ----------------
__global__ void k_hist(const float* __restrict__ xyz) {
    int i = blockIdx.x*256 + threadIdx.x;
    int b = i >> 13;
    float lo = fdec(g_bblo[b]);
    float inv = (float)NBINS / (fdec(g_bbhi[b]) - lo + 1e-4f);
    atomicAdd(&g_cnt[b*NBINS + xbin(xyz[3*i], lo, inv)], 1u);
}

// ---------------- exclusive scan (256 bins per batch) ----------------
__global__ void k_scan() {   // grid NB, block 256
    int b = blockIdx.x, tid = threadIdx.x, lane = tid & 31, wid = tid >> 5;
    __shared__ unsigned ws[8];
    unsigned v = g_cnt[b*NBINS + tid], s = v;
    #pragma unroll
    for (int off = 1; off < 32; off <<= 1) {
        unsigned n = __shfl_up_sync(0xffffffffu, s, off);
        if (lane >= off) s += n;
    }
    if (lane == 31) ws[wid] = s;
    __syncthreads();
    if (wid == 0 && lane < 8) {
        unsigned t = ws[lane];
        #pragma unroll
        for (int off = 1; off < 8; off <<= 1) {
            unsigned n = __shfl_up_sync(0xFFu, t, off, 8);
            if (lane >= off) t += n;
        }
        ws[lane] = t;
    }
    __syncthreads();
    unsigned excl = s - v + (wid ? ws[wid-1] : 0u);
    g_off[b*NBINS + tid] = excl;
    g_cur[b*NBINS + tid] = excl;
}

// ---------------- scatter into sorted order ----------------
__global__ void k_scatter(const float* __restrict__ xyz) {
    int i = blockIdx.x*256 + threadIdx.x;
    int b = i >> 13;
    float lo = fdec(g_bblo[b]);
    float inv = (float)NBINS / (fdec(g_bbhi[b]) - lo + 1e-4f);
    int bin = xbin(xyz[3*i], lo, inv);
    unsigned pos = atomicAdd(&g_cur[b*NBINS + bin], 1u);
    int slot = b*NPTS + (int)pos;
    g_spts[slot] = g_xyzw[i];
    g_sidx[slot] = i & (NPTS-1);
    g_sbin[slot] = (unsigned char)bin;
}

// ---------------- kNN: x-window scan, smem tiles, exact tile-edge bound ----------------
__global__ void __launch_bounds__(256) k_knn() {
    __shared__ float4 tile[8][TPW];    // 16KB, one 128-slot tile per warp
    int w = threadIdx.x >> 5, lane = threadIdx.x & 31;
    int qslot0 = blockIdx.x*256 + w*32;
    int b = qslot0 >> 13, bbase = b*NPTS;
    int ql = qslot0 & (NPTS-1);        // batch-local base
    int slot = qslot0 + lane;
    float4 qc = g_spts[slot];
    float qx = -0.5f*qc.x, qy = -0.5f*qc.y, qz = -0.5f*qc.z, qw = qc.w;

    float lo = fdec(g_bblo[b]);
    float h = (fdec(g_bbhi[b]) - lo + 1e-4f) / (float)NBINS;

    float kk[KNN]; int ii[KNN];
    #pragma unroll
    for (int s = 0; s < KNN; ++s) { kk[s] = CUDART_INF_F; ii[s] = 0; }
    float pkey = 0.f; int psl = 0; bool pval = false;

#define KNN_FLUSH() do {                                              \
        float ck = pkey; int ci = psl;                                \
        _Pragma("unroll")                                             \
        for (int s = 0; s < KNN; ++s) {                               \
            bool sw = ck < kk[s];                                     \
            float tk = kk[s]; int ti = ii[s];                         \
            kk[s] = sw ? ck : tk;  ii[s] = sw ? ci : ti;              \
            ck = sw ? tk : ck;     ci = sw ? ti : ci;                 \
        }                                                             \
    } while (0)

#define SCAN_TILE(T0) do {                                            \
        __syncwarp();                                                 \
        _Pragma("unroll")                                             \
        for (int i_ = 0; i_ < TPW/32; ++i_)                           \
            tile[w][lane + i_*32] = g_spts[bbase + (T0) + lane + i_*32]; \
        __syncwarp();                                                 \
        float thr = kk[KNN-1];                                        \
        _Pragma("unroll 8")                                           \
        for (int j_ = 0; j_ < TPW; ++j_) {                            \
            float4 c = tile[w][j_];                                   \
            float key = fmaf(c.x, qx, fmaf(c.y, qy, fmaf(c.z, qz, c.w))); \
            bool hit = key < thr;                                     \
            if (__any_sync(0xffffffffu, hit && pval)) {               \
                if (pval) { KNN_FLUSH(); thr = kk[KNN-1]; }           \
                pval = false;                                         \
            }                                                         \
            if (hit) { pkey = key; psl = (T0) + j_; pval = true; }    \
        }                                                             \
        if (__any_sync(0xffffffffu, pval)) {                          \
            if (pval) KNN_FLUSH();                                    \
            pval = false;                                             \
        }                                                             \
    } while (0)

    int tC = ql & ~(TPW-1);
    SCAN_TILE(tC);

    int tR = tC + TPW, tL = tC - TPW;
    bool rdone = (tR >= NPTS), ldone = (tL < 0);
    while (!(rdone && ldone)) {
        if (!rdone) {
            float d2 = kk[KNN-1] + qw;     // dist^2 of current 16th (finite after tile 1)
            // every slot >= tR has x >= lo + bin[tR]*h
            float xmin = fmaf((float)g_sbin[bbase + tR], h, lo);
            float dx = xmin - qx - 1e-5f;  // safety vs binning rounding
            bool sat = (dx > 0.f) && (dx*dx >= d2);
            if (__all_sync(0xffffffffu, sat)) rdone = true;
            else { SCAN_TILE(tR); tR += TPW; rdone = (tR >= NPTS); }
        }
        if (!ldone) {
            float d2 = kk[KNN-1] + qw;
            // every slot < tL+TPW has x < lo + (bin[tL+TPW-1]+1)*h
            float xmax = fmaf((float)(g_sbin[bbase + tL + TPW-1] + 1), h, lo);
            float dx = qx - xmax - 1e-5f;
            bool sat = (dx > 0.f) && (dx*dx >= d2);
            if (__all_sync(0xffffffffu, sat)) ldone = true;
            else { SCAN_TILE(tL); tL -= TPW; ldone = (tL < 0); }
        }
    }
#undef SCAN_TILE
#undef KNN_FLUSH

    int oq = g_sidx[slot];
    int* op = g_idx + (size_t)(bbase + oq)*KNN;
    #pragma unroll
    for (int s = 0; s < KNN; ++s) op[s] = g_sidx[bbase + ii[s]];
}

// ---------------- v = feat @ Wv + bv ----------------
__global__ void k_gemm_v(const float* __restrict__ feat, const float* __restrict__ Wv,
                         const float* __restrict__ bv) {
    __shared__ float As[16][132];
    __shared__ float Ws[16][132];
    int m0 = blockIdx.x*128;
    int tx = threadIdx.x & 15, ty = threadIdx.x >> 4;
    float acc[8][8];
    #pragma unroll
    for (int i = 0; i < 8; ++i)
        #pragma unroll
        for (int j = 0; j < 8; ++j) acc[i][j] = 0.f;

    for (int kc = 0; kc < D; kc += 16) {
        __syncthreads();
        { int c = threadIdx.x & 3, r = threadIdx.x >> 2;
          #pragma unroll
          for (int rr = 0; rr < 2; ++rr) {
              int mm = r + rr*64;
              float4 v = *(const float4*)&feat[(size_t)(m0+mm)*D + kc + c*4];
              As[c*4+0][mm] = v.x; As[c*4+1][mm] = v.y;
              As[c*4+2][mm] = v.z; As[c*4+3][mm] = v.w;
          }
        }
        { int k = threadIdx.x >> 5, c4 = threadIdx.x & 31;
          #pragma unroll
          for (int kk = 0; kk < 2; ++kk) {
              float4 v = *(const float4*)&Wv[(size_t)(kc + k + kk*8)*D + c4*4];
              Ws[k + kk*8][c4*4+0] = v.x; Ws[k + kk*8][c4*4+1] = v.y;
              Ws[k + kk*8][c4*4+2] = v.z; Ws[k + kk*8][c4*4+3] = v.w;
          }
        }
        __syncthreads();
        #pragma unroll
        for (int k = 0; k < 16; ++k) {
            float a[8], bb[8];
            #pragma unroll
            for (int i = 0; i < 8; ++i) a[i]  = As[k][ty*8 + i];
            #pragma unroll
            for (int j = 0; j < 8; ++j) bb[j] = Ws[k][tx*8 + j];
            #pragma unroll
            for (int i = 0; i < 8; ++i)
                #pragma unroll
                for (int j = 0; j < 8; ++j) acc[i][j] = fmaf(a[i], bb[j], acc[i][j]);
        }
    }
    #pragma unroll
    for (int i = 0; i < 8; ++i) {
        int m = m0 + ty*8 + i;
        #pragma unroll
        for (int j = 0; j < 8; ++j) acc[i][j] += bv[tx*8 + j];
        *(float4*)&g_v[(size_t)m*D + tx*8]     = make_float4(acc[i][0], acc[i][1], acc[i][2], acc[i][3]);
        *(float4*)&g_v[(size_t)m*D + tx*8 + 4] = make_float4(acc[i][4], acc[i][5], acc[i][6], acc[i][7]);
    }
}

// ---------------- fused attention (warp per point) ----------------
__global__ void k_fuse(const float* __restrict__ xyz, const float* __restrict__ Wp1,
                       const float* __restrict__ bp1) {
    __shared__ float sw0[D], sw1[D], sw2[D], sb1[D], srs[D];
    int tid = threadIdx.x;
    sw0[tid] = Wp1[tid]; sw1[tid] = Wp1[D + tid]; sw2[tid] = Wp1[2*D + tid];
    sb1[tid] = bp1[tid]; srs[tid] = g_wp2rs[tid];
    __syncthreads();

    int warp = tid >> 5, lane = tid & 31;
    int p = blockIdx.x*4 + warp;
    int bbase = p & ~(NPTS-1);

    float w0[4], w1[4], w2[4], b1r[4], rs[4];
    #pragma unroll
    for (int i = 0; i < 4; ++i) {
        int d = lane + 32*i;
        w0[i] = sw0[d]; w1[i] = sw1[d]; w2[i] = sw2[d]; b1r[i] = sb1[d]; rs[i] = srs[d];
    }

    float rx = 0.f, ry = 0.f, rz = 0.f, ks = 0.f; int row = 0;
    if (lane < KNN) {
        int nb = g_idx[(size_t)p*KNN + lane];
        row = bbase + nb;
        float qx = xyz[3*p], qy = xyz[3*p+1], qz = xyz[3*p+2];
        rx = qx - xyz[3*row]; ry = qy - xyz[3*row+1]; rz = qz - xyz[3*row+2];
        ks = g_ksum[row];
    }

    float mysc = -CUDART_INF_F;
    #pragma unroll
    for (int k = 0; k < KNN; ++k) {
        float bx = __shfl_sync(0xffffffffu, rx, k);
        float by = __shfl_sync(0xffffffffu, ry, k);
        float bz = __shfl_sync(0xffffffffu, rz, k);
        float part = 0.f;
        #pragma unroll
        for (int i = 0; i < 4; ++i) {
            float h = fmaf(bx, w0[i], fmaf(by, w1[i], fmaf(bz, w2[i], b1r[i])));
            h = fmaxf(h, 0.f);
            part = fmaf(h, rs[i], part);
        }
        #pragma unroll
        for (int off = 16; off; off >>= 1) part += __shfl_xor_sync(0xffffffffu, part, off);
        if (lane == k) mysc = part - ks;
    }
    float mx = mysc;
    #pragma unroll
    for (int off = 16; off; off >>= 1) mx = fmaxf(mx, __shfl_xor_sync(0xffffffffu, mx, off));
    float e = (lane < KNN) ? __expf(mysc - mx) : 0.f;
    float ssum = e;
    #pragma unroll
    for (int off = 16; off; off >>= 1) ssum += __shfl_xor_sync(0xffffffffu, ssum, off);
    float attn = e / ssum;

    float hb[4] = {0,0,0,0}, vb[4] = {0,0,0,0};
    #pragma unroll
    for (int k = 0; k < KNN; ++k) {
        float a  = __shfl_sync(0xffffffffu, attn, k);
        float bx = __shfl_sync(0xffffffffu, rx, k);
        float by = __shfl_sync(0xffffffffu, ry, k);
        float bz = __shfl_sync(0xffffffffu, rz, k);
        int   r  = __shfl_sync(0xffffffffu, row, k);
        const float* vr = g_v + (size_t)r*D;
        #pragma unroll
        for (int i = 0; i < 4; ++i) {
            int d = lane + 32*i;
            float h = fmaf(bx, w0[i], fmaf(by, w1[i], fmaf(bz, w2[i], b1r[i])));
            h = fmaxf(h, 0.f);
            hb[i] = fmaf(a, h, hb[i]);
            vb[i] = fmaf(a, vr[d], vb[i]);
        }
    }
    #pragma unroll
    for (int i = 0; i < 4; ++i) {
        int d = lane + 32*i;
        g_hbar[(size_t)p*D + d] = hb[i];
        g_vbar[(size_t)p*D + d] = vb[i];
    }
}

// ---------------- out = feat + gamma*(vbar@Wo + hbar@Wf + cvec) ----------------
__global__ void k_out(const float* __restrict__ feat, const float* __restrict__ Wo,
                      const float* __restrict__ gamma, float* __restrict__ out) {
    __shared__ float As[16][132];
    __shared__ float Ws[16][132];
    int m0 = blockIdx.x*128;
    int tx = threadIdx.x & 15, ty = threadIdx.x >> 4;
    float acc[8][8];
    #pragma unroll
    for (int i = 0; i < 8; ++i)
        #pragma unroll
        for (int j = 0; j < 8; ++j) acc[i][j] = 0.f;

    for (int ph = 0; ph < 2; ++ph) {
        const float* A = ph ? g_hbar : g_vbar;
        const float* W = ph ? g_wf   : Wo;
        for (int kc = 0; kc < D; kc += 16) {
            __syncthreads();
            { int c = threadIdx.x & 3, r = threadIdx.x >> 2;
              #pragma unroll
              for (int rr = 0; rr < 2; ++rr) {
                  int mm = r + rr*64;
                  float4 v = *(const float4*)&A[(size_t)(m0+mm)*D + kc + c*4];
                  As[c*4+0][mm] = v.x; As[c*4+1][mm] = v.y;
                  As[c*4+2][mm] = v.z; As[c*4+3][mm] = v.w;
              }
            }
            { int k = threadIdx.x >> 5, c4 = threadIdx.x & 31;
              #pragma unroll
              for (int kk = 0; kk < 2; ++kk) {
                  float4 v = *(const float4*)&W[(size_t)(kc + k + kk*8)*D + c4*4];
                  Ws[k + kk*8][c4*4+0] = v.x; Ws[k + kk*8][c4*4+1] = v.y;
                  Ws[k + kk*8][c4*4+2] = v.z; Ws[k + kk*8][c4*4+3] = v.w;
              }
            }
            __syncthreads();
            #pragma unroll
            for (int k = 0; k < 16; ++k) {
                float a[8], bb[8];
                #pragma unroll
                for (int i = 0; i < 8; ++i) a[i]  = As[k][ty*8 + i];
                #pragma unroll
                for (int j = 0; j < 8; ++j) bb[j] = Ws[k][tx*8 + j];
                #pragma unroll
                for (int i = 0; i < 8; ++i)
                    #pragma unroll
                    for (int j = 0; j < 8; ++j) acc[i][j] = fmaf(a[i], bb[j], acc[i][j]);
            }
        }
    }
    float g = *gamma;
    float cv[8];
    #pragma unroll
    for (int j = 0; j < 8; ++j) cv[j] = g_cvec[tx*8 + j];
    #pragma unroll
    for (int i = 0; i < 8; ++i) {
        int m = m0 + ty*8 + i;
        float4 f0 = *(const float4*)&feat[(size_t)m*D + tx*8];
        float4 f1 = *(const float4*)&feat[(size_t)m*D + tx*8 + 4];
        float o0 = f0.x + g*(acc[i][0] + cv[0]);
        float o1 = f0.y + g*(acc[i][1] + cv[1]);
        float o2 = f0.z + g*(acc[i][2] + cv[2]);
        float o3 = f0.w + g*(acc[i][3] + cv[3]);
        float o4 = f1.x + g*(acc[i][4] + cv[4]);
        float o5 = f1.y + g*(acc[i][5] + cv[5]);
        float o6 = f1.z + g*(acc[i][6] + cv[6]);
        float o7 = f1.w + g*(acc[i][7] + cv[7]);
        *(float4*)&out[(size_t)m*D + tx*8]     = make_float4(o0, o1, o2, o3);
        *(float4*)&out[(size_t)m*D + tx*8 + 4] = make_float4(o4, o5, o6, o7);
    }
}

// ---------------- launch ----------------
extern "C" void kernel_launch(void* const* d_in, const int* in_sizes, int n_in,
                              void* d_out, int out_size) {
    const float* xyz  = (const float*)d_in[0];
    const float* feat = (const float*)d_in[1];
    // d_in[2]=Wq, d_in[3]=bq, d_in[5]=bk : mathematically cancel in softmax, unused
    const float* Wk   = (const float*)d_in[4];
    const float* Wv   = (const float*)d_in[6];
    const float* bv   = (const float*)d_in[7];
    const float* Wp1  = (const float*)d_in[8];
    const float* bp1  = (const float*)d_in[9];
    const float* Wp2  = (const float*)d_in[10];
    const float* bp2  = (const float*)d_in[11];
    const float* Wo   = (const float*)d_in[12];
    const float* bo   = (const float*)d_in[13];
    const float* gmm  = (const float*)d_in[14];
    float* out = (float*)d_out;

    k_zero<<<1, 1024>>>();
    k_weights<<<1, 128>>>(Wk, Wp2, bp2, Wo, bo);
    k_wfused<<<64, 256>>>(Wp2, Wo);
    k_prep<<<BN/8, 256>>>(xyz, feat);
    k_hist<<<BN/256, 256>>>(xyz);
    k_scan<<<NB, 256>>>();
    k_scatter<<<BN/256, 256>>>(xyz);
    k_knn<<<BN/256, 256>>>();
    k_gemm_v<<<BN/128, 256>>>(feat, Wv, bv);
    k_fuse<<<BN/4, 128>>>(xyz, Wp1, bp1);
    k_out<<<BN/128, 256>>>(feat, Wo, gmm, out);
}

// round 10
// speedup vs baseline: 23.2389x; 1.2760x over previous
#include <cuda_runtime.h>
#include <math.h>
#include <math_constants.h>

#define NB   4
#define NPTS 8192
#define BN   (NB*NPTS)   // 32768
#define D    128
#define KNN  16
#define NBINS 256
#define TPW  128         // tile slots per warp
#define NW   4           // warps per query group

// ---------------- scratch (static device allocations) ----------------
__device__ float4   g_xyzw[BN];        // (-2x,-2y,-2z, |x|^2) per point (orig order)
__device__ float4   g_spts[BN];        // same, sorted by (batch, x-bin)
__device__ int      g_sidx[BN];        // sorted slot -> original local idx
__device__ unsigned char g_sbin[BN];   // sorted slot -> bin
__device__ unsigned g_cnt[NB*NBINS];   // histogram
__device__ unsigned g_off[NB*NBINS];   // bin start offsets (batch-local)
__device__ unsigned g_cur[NB*NBINS];   // scatter cursors
__device__ unsigned g_bblo[NB], g_bbhi[NB];      // encoded x-bbox
__device__ float  g_ksum[BN];          // feat . rowsum(Wk)
__device__ int    g_idx[BN*KNN];       // knn indices (within batch)
__device__ float  g_v[BN*D];           // feat @ Wv + bv
__device__ float  g_hbar[BN*D];        // sum_k attn_k * h_k
__device__ float  g_vbar[BN*D];        // sum_k attn_k * v_k
__device__ float  g_wkrs[D];           // rowsum over out-dim of Wk
__device__ float  g_wp2rs[D];          // rowsum over out-dim of Wp2
__device__ float  g_cvec[D];           // bp2 @ Wo + bo
__device__ float  g_wf[D*D];           // Wp2 @ Wo

// ---------------- helpers ----------------
__device__ __forceinline__ unsigned fenc(float f) {
    unsigned u = __float_as_uint(f);
    return (u & 0x80000000u) ? ~u : (u | 0x80000000u);
}
__device__ __forceinline__ float fdec(unsigned u) {
    return (u & 0x80000000u) ? __uint_as_float(u ^ 0x80000000u) : __uint_as_float(~u);
}
__device__ __forceinline__ int xbin(float x, float lo, float inv) {
    int v = (int)((x - lo) * inv);
    return v < 0 ? 0 : (v > NBINS-1 ? NBINS-1 : v);
}

// ---------------- init ----------------
__global__ void k_zero() {   // 1 block, 1024 threads
    int i = threadIdx.x;
    g_cnt[i] = 0;
    if (i < NB) { g_bblo[i] = 0xFFFFFFFFu; g_bbhi[i] = 0u; }
}

// ---------------- weight prep ----------------
__global__ void k_weights(const float* __restrict__ Wk, const float* __restrict__ Wp2,
                          const float* __restrict__ bp2, const float* __restrict__ Wo,
                          const float* __restrict__ bo) {
    int i = threadIdx.x;
    float a = 0.f, b = 0.f, c = bo[i];
    for (int j = 0; j < D; ++j) { a += Wk[i*D + j]; b += Wp2[i*D + j]; }
    for (int k = 0; k < D; ++k) c = fmaf(bp2[k], Wo[k*D + i], c);
    g_wkrs[i] = a; g_wp2rs[i] = b; g_cvec[i] = c;
}

__global__ void k_wfused(const float* __restrict__ Wp2, const float* __restrict__ Wo) {
    int d = threadIdx.x & (D-1);
    int i = blockIdx.x*2 + (threadIdx.x >> 7);
    float a = 0.f;
    for (int k = 0; k < D; ++k) a = fmaf(Wp2[i*D + k], Wo[k*D + d], a);
    g_wf[i*D + d] = a;
}

// ---------------- per-point prep: xyzw + ksum + x-bbox ----------------
__global__ void k_prep(const float* __restrict__ xyz, const float* __restrict__ feat) {
    __shared__ unsigned slo, shi;
    if (threadIdx.x == 0) { slo = 0xFFFFFFFFu; shi = 0u; }
    __syncthreads();
    int warp = threadIdx.x >> 5, lane = threadIdx.x & 31;
    int p = blockIdx.x*8 + warp;
    const float* fr = feat + (size_t)p*D;
    float acc = 0.f;
    #pragma unroll
    for (int i = 0; i < 4; ++i) {
        int d = lane + 32*i;
        acc = fmaf(fr[d], g_wkrs[d], acc);
    }
    #pragma unroll
    for (int off = 16; off; off >>= 1) acc += __shfl_xor_sync(0xffffffffu, acc, off);
    if (lane == 0) {
        g_ksum[p] = acc;
        float x = xyz[3*p], y = xyz[3*p+1], z = xyz[3*p+2];
        g_xyzw[p] = make_float4(-2.f*x, -2.f*y, -2.f*z, x*x + y*y + z*z);
        unsigned e = fenc(x);
        atomicMin(&slo, e); atomicMax(&shi, e);
    }
    __syncthreads();
    if (threadIdx.x == 0) {
        int b = (blockIdx.x*8) >> 13;
        atomicMin(&g_bblo[b], slo); atomicMax(&g_bbhi[b], shi);
    }
}

// ---------------- histogram over x-bins ----------------
__global__ void k_hist(const float* __restrict__ xyz) {
    int i = blockIdx.x*256 + threadIdx.x;
    int b = i >> 13;
    float lo = fdec(g_bblo[b]);
    float inv = (float)NBINS / (fdec(g_bbhi[b]) - lo + 1e-4f);
    atomicAdd(&g_cnt[b*NBINS + xbin(xyz[3*i], lo, inv)], 1u);
}

// ---------------- exclusive scan (256 bins per batch) ----------------
__global__ void k_scan() {   // grid NB, block 256
    int b = blockIdx.x, tid = threadIdx.x, lane = tid & 31, wid = tid >> 5;
    __shared__ unsigned ws[8];
    unsigned v = g_cnt[b*NBINS + tid], s = v;
    #pragma unroll
    for (int off = 1; off < 32; off <<= 1) {
        unsigned n = __shfl_up_sync(0xffffffffu, s, off);
        if (lane >= off) s += n;
    }
    if (lane == 31) ws[wid] = s;
    __syncthreads();
    if (wid == 0 && lane < 8) {
        unsigned t = ws[lane];
        #pragma unroll
        for (int off = 1; off < 8; off <<= 1) {
            unsigned n = __shfl_up_sync(0xFFu, t, off, 8);
            if (lane >= off) t += n;
        }
        ws[lane] = t;
    }
    __syncthreads();
    unsigned excl = s - v + (wid ? ws[wid-1] : 0u);
    g_off[b*NBINS + tid] = excl;
    g_cur[b*NBINS + tid] = excl;
}

// ---------------- scatter into sorted order ----------------
__global__ void k_scatter(const float* __restrict__ xyz) {
    int i = blockIdx.x*256 + threadIdx.x;
    int b = i >> 13;
    float lo = fdec(g_bblo[b]);
    float inv = (float)NBINS / (fdec(g_bbhi[b]) - lo + 1e-4f);
    int bin = xbin(xyz[3*i], lo, inv);
    unsigned pos = atomicAdd(&g_cur[b*NBINS + bin], 1u);
    int slot = b*NPTS + (int)pos;
    g_spts[slot] = g_xyzw[i];
    g_sidx[slot] = i & (NPTS-1);
    g_sbin[slot] = (unsigned char)bin;
}

// ---------------- kNN: 4-warp split x-window scan, warm-started ----------------
__global__ void __launch_bounds__(128) k_knn() {
    __shared__ float4 tile[NW][TPW];       // 8KB, one 128-slot tile per warp
    __shared__ float  sth[NW][32];         // per-(warp,query) 16th-dist^2
    __shared__ float  md[KNN*NW*32];       // merge keys
    __shared__ int    mi[KNN*NW*32];       // merge slot ids

    int w = threadIdx.x >> 5, lane = threadIdx.x & 31;
    int qslot0 = blockIdx.x*32;            // 32 consecutive sorted queries
    int b = qslot0 >> 13, bbase = b*NPTS;
    int ql = qslot0 & (NPTS-1);
    int slot = qslot0 + lane;
    float4 qc = g_spts[slot];
    float qx = -0.5f*qc.x, qy = -0.5f*qc.y, qz = -0.5f*qc.z, qw = qc.w;

    float lo = fdec(g_bblo[b]);
    float h = (fdec(g_bbhi[b]) - lo + 1e-4f) / (float)NBINS;

    volatile float* sv = &sth[0][0];
    sth[w][lane] = CUDART_INF_F;

    float kk[KNN]; int ii[KNN];
    #pragma unroll
    for (int s = 0; s < KNN; ++s) { kk[s] = CUDART_INF_F; ii[s] = 0; }
    float pkey = 0.f; int psl = 0; bool pval = false;

#define KNN_FLUSH() do {                                              \
        float ck = pkey; int ci = psl;                                \
        _Pragma("unroll")                                             \
        for (int s = 0; s < KNN; ++s) {                               \
            bool sw = ck < kk[s];                                     \
            float tk = kk[s]; int ti = ii[s];                         \
            kk[s] = sw ? ck : tk;  ii[s] = sw ? ci : ti;              \
            ck = sw ? tk : ck;     ci = sw ? ti : ci;                 \
        }                                                             \
    } while (0)

#define SCAN_TILE(T0, CAP) do {                                       \
        __syncwarp();                                                 \
        _Pragma("unroll")                                             \
        for (int i_ = 0; i_ < TPW/32; ++i_)                           \
            tile[w][lane + i_*32] = g_spts[bbase + (T0) + lane + i_*32]; \
        __syncwarp();                                                 \
        float thr = fminf(kk[KNN-1], (CAP));                          \
        _Pragma("unroll 8")                                           \
        for (int j_ = 0; j_ < TPW; ++j_) {                            \
            float4 c = tile[w][j_];                                   \
            float key = fmaf(c.x, qx, fmaf(c.y, qy, fmaf(c.z, qz, c.w))); \
            bool hit = key < thr;                                     \
            if (__any_sync(0xffffffffu, hit && pval)) {               \
                if (pval) { KNN_FLUSH(); thr = fminf(kk[KNN-1], (CAP)); } \
                pval = false;                                         \
            }                                                         \
            if (hit) { pkey = key; psl = (T0) + j_; pval = true; }    \
        }                                                             \
        if (__any_sync(0xffffffffu, pval)) {                          \
            if (pval) KNN_FLUSH();                                    \
            pval = false;                                             \
        }                                                             \
        sth[w][lane] = kk[KNN-1] + qw;                                \
    } while (0)

    __syncthreads();
    int tC = ql & ~(TPW-1);
    if (w == 0) SCAN_TILE(tC, CUDART_INF_F);   // warm-start: center tile
    __syncthreads();

    // Each warp owns ONE side with stride 2:
    //   warp0: right k=1,3,5,...   warp2: right k=2,4,6,...
    //   warp1: left  k=1,3,5,...   warp3: left  k=2,4,6,...
    // A warp exits when its side runs off the array or its own prune fires
    // (dx monotone per side -> prune covers all its farther tiles).
    int side = w & 1;
    for (int k = 1 + (w >> 1); k <= NPTS/TPW; k += 2) {
        float d2s = fminf(fminf(sv[lane], sv[32+lane]), fminf(sv[64+lane], sv[96+lane]));
        d2s = fminf(d2s, kk[KNN-1] + qw);
        if (side == 0) {
            int T0 = tC + k*TPW;
            if (T0 >= NPTS) break;
            float xmin = fmaf((float)g_sbin[bbase + T0], h, lo);
            float dx = xmin - qx - 1e-5f;
            if (__all_sync(0xffffffffu, (dx > 0.f) && (dx*dx >= d2s))) break;
            SCAN_TILE(T0, d2s - qw);
        } else {
            int T0 = tC - k*TPW;
            if (T0 < 0) break;
            float xmax = fmaf((float)(g_sbin[bbase + T0 + TPW-1] + 1), h, lo);
            float dx = qx - xmax - 1e-5f;
            if (__all_sync(0xffffffffu, (dx > 0.f) && (dx*dx >= d2s))) break;
            SCAN_TILE(T0, d2s - qw);
        }
    }
#undef SCAN_TILE
#undef KNN_FLUSH

    // ---- 4-way merge of sorted 16-lists (disjoint tiles -> no duplicates) ----
    #pragma unroll
    for (int s = 0; s < KNN; ++s) {
        md[s*(NW*32) + w*32 + lane] = kk[s];
        mi[s*(NW*32) + w*32 + lane] = ii[s];
    }
    __syncthreads();
    if (w == 0) {
        int p0 = 0, p1 = 0, p2 = 0, p3 = 0;
        int oq = g_sidx[slot];
        int* op = g_idx + (size_t)(bbase + oq)*KNN;
        #pragma unroll
        for (int s = 0; s < KNN; ++s) {
            float h0 = md[p0*128 +  0 + lane];
            float h1 = md[p1*128 + 32 + lane];
            float h2 = md[p2*128 + 64 + lane];
            float h3 = md[p3*128 + 96 + lane];
            float best = h0; int bw = 0;
            if (h1 < best) { best = h1; bw = 1; }
            if (h2 < best) { best = h2; bw = 2; }
            if (h3 < best) { best = h3; bw = 3; }
            int pj = (bw == 0) ? p0 : (bw == 1) ? p1 : (bw == 2) ? p2 : p3;
            int sl = mi[pj*128 + bw*32 + lane];
            op[s] = g_sidx[bbase + sl];
            if (bw == 0) ++p0; else if (bw == 1) ++p1; else if (bw == 2) ++p2; else ++p3;
        }
    }
}

// ---------------- v = feat @ Wv + bv ----------------
__global__ void k_gemm_v(const float* __restrict__ feat, const float* __restrict__ Wv,
                         const float* __restrict__ bv) {
    __shared__ float As[16][132];
    __shared__ float Ws[16][132];
    int m0 = blockIdx.x*128;
    int tx = threadIdx.x & 15, ty = threadIdx.x >> 4;
    float acc[8][8];
    #pragma unroll
    for (int i = 0; i < 8; ++i)
        #pragma unroll
        for (int j = 0; j < 8; ++j) acc[i][j] = 0.f;

    for (int kc = 0; kc < D; kc += 16) {
        __syncthreads();
        { int c = threadIdx.x & 3, r = threadIdx.x >> 2;
          #pragma unroll
          for (int rr = 0; rr < 2; ++rr) {
              int mm = r + rr*64;
              float4 v = *(const float4*)&feat[(size_t)(m0+mm)*D + kc + c*4];
              As[c*4+0][mm] = v.x; As[c*4+1][mm] = v.y;
              As[c*4+2][mm] = v.z; As[c*4+3][mm] = v.w;
          }
        }
        { int k = threadIdx.x >> 5, c4 = threadIdx.x & 31;
          #pragma unroll
          for (int kk = 0; kk < 2; ++kk) {
              float4 v = *(const float4*)&Wv[(size_t)(kc + k + kk*8)*D + c4*4];
              Ws[k + kk*8][c4*4+0] = v.x; Ws[k + kk*8][c4*4+1] = v.y;
              Ws[k + kk*8][c4*4+2] = v.z; Ws[k + kk*8][c4*4+3] = v.w;
          }
        }
        __syncthreads();
        #pragma unroll
        for (int k = 0; k < 16; ++k) {
            float a[8], bb[8];
            #pragma unroll
            for (int i = 0; i < 8; ++i) a[i]  = As[k][ty*8 + i];
            #pragma unroll
            for (int j = 0; j < 8; ++j) bb[j] = Ws[k][tx*8 + j];
            #pragma unroll
            for (int i = 0; i < 8; ++i)
                #pragma unroll
                for (int j = 0; j < 8; ++j) acc[i][j] = fmaf(a[i], bb[j], acc[i][j]);
        }
    }
    #pragma unroll
    for (int i = 0; i < 8; ++i) {
        int m = m0 + ty*8 + i;
        #pragma unroll
        for (int j = 0; j < 8; ++j) acc[i][j] += bv[tx*8 + j];
        *(float4*)&g_v[(size_t)m*D + tx*8]     = make_float4(acc[i][0], acc[i][1], acc[i][2], acc[i][3]);
        *(float4*)&g_v[(size_t)m*D + tx*8 + 4] = make_float4(acc[i][4], acc[i][5], acc[i][6], acc[i][7]);
    }
}

// ---------------- fused attention (warp per point) ----------------
__global__ void k_fuse(const float* __restrict__ xyz, const float* __restrict__ Wp1,
                       const float* __restrict__ bp1) {
    __shared__ float sw0[D], sw1[D], sw2[D], sb1[D], srs[D];
    int tid = threadIdx.x;
    sw0[tid] = Wp1[tid]; sw1[tid] = Wp1[D + tid]; sw2[tid] = Wp1[2*D + tid];
    sb1[tid] = bp1[tid]; srs[tid] = g_wp2rs[tid];
    __syncthreads();

    int warp = tid >> 5, lane = tid & 31;
    int p = blockIdx.x*4 + warp;
    int bbase = p & ~(NPTS-1);

    float w0[4], w1[4], w2[4], b1r[4], rs[4];
    #pragma unroll
    for (int i = 0; i < 4; ++i) {
        int d = lane + 32*i;
        w0[i] = sw0[d]; w1[i] = sw1[d]; w2[i] = sw2[d]; b1r[i] = sb1[d]; rs[i] = srs[d];
    }

    float rx = 0.f, ry = 0.f, rz = 0.f, ks = 0.f; int row = 0;
    if (lane < KNN) {
        int nb = g_idx[(size_t)p*KNN + lane];
        row = bbase + nb;
        float qx = xyz[3*p], qy = xyz[3*p+1], qz = xyz[3*p+2];
        rx = qx - xyz[3*row]; ry = qy - xyz[3*row+1]; rz = qz - xyz[3*row+2];
        ks = g_ksum[row];
    }

    float mysc = -CUDART_INF_F;
    #pragma unroll
    for (int k = 0; k < KNN; ++k) {
        float bx = __shfl_sync(0xffffffffu, rx, k);
        float by = __shfl_sync(0xffffffffu, ry, k);
        float bz = __shfl_sync(0xffffffffu, rz, k);
        float part = 0.f;
        #pragma unroll
        for (int i = 0; i < 4; ++i) {
            float h = fmaf(bx, w0[i], fmaf(by, w1[i], fmaf(bz, w2[i], b1r[i])));
            h = fmaxf(h, 0.f);
            part = fmaf(h, rs[i], part);
        }
        #pragma unroll
        for (int off = 16; off; off >>= 1) part += __shfl_xor_sync(0xffffffffu, part, off);
        if (lane == k) mysc = part - ks;
    }
    float mx = mysc;
    #pragma unroll
    for (int off = 16; off; off >>= 1) mx = fmaxf(mx, __shfl_xor_sync(0xffffffffu, mx, off));
    float e = (lane < KNN) ? __expf(mysc - mx) : 0.f;
    float ssum = e;
    #pragma unroll
    for (int off = 16; off; off >>= 1) ssum += __shfl_xor_sync(0xffffffffu, ssum, off);
    float attn = e / ssum;

    float hb[4] = {0,0,0,0}, vb[4] = {0,0,0,0};
    #pragma unroll
    for (int k = 0; k < KNN; ++k) {
        float a  = __shfl_sync(0xffffffffu, attn, k);
        float bx = __shfl_sync(0xffffffffu, rx, k);
        float by = __shfl_sync(0xffffffffu, ry, k);
        float bz = __shfl_sync(0xffffffffu, rz, k);
        int   r  = __shfl_sync(0xffffffffu, row, k);
        const float* vr = g_v + (size_t)r*D;
        #pragma unroll
        for (int i = 0; i < 4; ++i) {
            int d = lane + 32*i;
            float h = fmaf(bx, w0[i], fmaf(by, w1[i], fmaf(bz, w2[i], b1r[i])));
            h = fmaxf(h, 0.f);
            hb[i] = fmaf(a, h, hb[i]);
            vb[i] = fmaf(a, vr[d], vb[i]);
        }
    }
    #pragma unroll
    for (int i = 0; i < 4; ++i) {
        int d = lane + 32*i;
        g_hbar[(size_t)p*D + d] = hb[i];
        g_vbar[(size_t)p*D + d] = vb[i];
    }
}

// ---------------- out = feat + gamma*(vbar@Wo + hbar@Wf + cvec) ----------------
__global__ void k_out(const float* __restrict__ feat, const float* __restrict__ Wo,
                      const float* __restrict__ gamma, float* __restrict__ out) {
    __shared__ float As[16][132];
    __shared__ float Ws[16][132];
    int m0 = blockIdx.x*128;
    int tx = threadIdx.x & 15, ty = threadIdx.x >> 4;
    float acc[8][8];
    #pragma unroll
    for (int i = 0; i < 8; ++i)
        #pragma unroll
        for (int j = 0; j < 8; ++j) acc[i][j] = 0.f;

    for (int ph = 0; ph < 2; ++ph) {
        const float* A = ph ? g_hbar : g_vbar;
        const float* W = ph ? g_wf   : Wo;
        for (int kc = 0; kc < D; kc += 16) {
            __syncthreads();
            { int c = threadIdx.x & 3, r = threadIdx.x >> 2;
              #pragma unroll
              for (int rr = 0; rr < 2; ++rr) {
                  int mm = r + rr*64;
                  float4 v = *(const float4*)&A[(size_t)(m0+mm)*D + kc + c*4];
                  As[c*4+0][mm] = v.x; As[c*4+1][mm] = v.y;
                  As[c*4+2][mm] = v.z; As[c*4+3][mm] = v.w;
              }
            }
            { int k = threadIdx.x >> 5, c4 = threadIdx.x & 31;
              #pragma unroll
              for (int kk = 0; kk < 2; ++kk) {
                  float4 v = *(const float4*)&W[(size_t)(kc + k + kk*8)*D + c4*4];
                  Ws[k + kk*8][c4*4+0] = v.x; Ws[k + kk*8][c4*4+1] = v.y;
                  Ws[k + kk*8][c4*4+2] = v.z; Ws[k + kk*8][c4*4+3] = v.w;
              }
            }
            __syncthreads();
            #pragma unroll
            for (int k = 0; k < 16; ++k) {
                float a[8], bb[8];
                #pragma unroll
                for (int i = 0; i < 8; ++i) a[i]  = As[k][ty*8 + i];
                #pragma unroll
                for (int j = 0; j < 8; ++j) bb[j] = Ws[k][tx*8 + j];
                #pragma unroll
                for (int i = 0; i < 8; ++i)
                    #pragma unroll
                    for (int j = 0; j < 8; ++j) acc[i][j] = fmaf(a[i], bb[j], acc[i][j]);
            }
        }
    }
    float g = *gamma;
    float cv[8];
    #pragma unroll
    for (int j = 0; j < 8; ++j) cv[j] = g_cvec[tx*8 + j];
    #pragma unroll
    for (int i = 0; i < 8; ++i) {
        int m = m0 + ty*8 + i;
        float4 f0 = *(const float4*)&feat[(size_t)m*D + tx*8];
        float4 f1 = *(const float4*)&feat[(size_t)m*D + tx*8 + 4];
        float o0 = f0.x + g*(acc[i][0] + cv[0]);
        float o1 = f0.y + g*(acc[i][1] + cv[1]);
        float o2 = f0.z + g*(acc[i][2] + cv[2]);
        float o3 = f0.w + g*(acc[i][3] + cv[3]);
        float o4 = f1.x + g*(acc[i][4] + cv[4]);
        float o5 = f1.y + g*(acc[i][5] + cv[5]);
        float o6 = f1.z + g*(acc[i][6] + cv[6]);
        float o7 = f1.w + g*(acc[i][7] + cv[7]);
        *(float4*)&out[(size_t)m*D + tx*8]     = make_float4(o0, o1, o2, o3);
        *(float4*)&out[(size_t)m*D + tx*8 + 4] = make_float4(o4, o5, o6, o7);
    }
}

// ---------------- launch ----------------
extern "C" void kernel_launch(void* const* d_in, const int* in_sizes, int n_in,
                              void* d_out, int out_size) {
    const float* xyz  = (const float*)d_in[0];
    const float* feat = (const float*)d_in[1];
    // d_in[2]=Wq, d_in[3]=bq, d_in[5]=bk : mathematically cancel in softmax, unused
    const float* Wk   = (const float*)d_in[4];
    const float* Wv   = (const float*)d_in[6];
    const float* bv   = (const float*)d_in[7];
    const float* Wp1  = (const float*)d_in[8];
    const float* bp1  = (const float*)d_in[9];
    const float* Wp2  = (const float*)d_in[10];
    const float* bp2  = (const float*)d_in[11];
    const float* Wo   = (const float*)d_in[12];
    const float* bo   = (const float*)d_in[13];
    const float* gmm  = (const float*)d_in[14];
    float* out = (float*)d_out;

    k_zero<<<1, 1024>>>();
    k_weights<<<1, 128>>>(Wk, Wp2, bp2, Wo, bo);
    k_wfused<<<64, 256>>>(Wp2, Wo);
    k_prep<<<BN/8, 256>>>(xyz, feat);
    k_hist<<<BN/256, 256>>>(xyz);
    k_scan<<<NB, 256>>>();
    k_scatter<<<BN/256, 256>>>(xyz);
    k_knn<<<BN/32, 128>>>();
    k_gemm_v<<<BN/128, 256>>>(feat, Wv, bv);
    k_fuse<<<BN/4, 128>>>(xyz, Wp1, bp1);
    k_out<<<BN/128, 256>>>(feat, Wo, gmm, out);
}

// round 11
// speedup vs baseline: 27.2554x; 1.1728x over previous
#include <cuda_runtime.h>
#include <math.h>
#include <math_constants.h>

#define NB   4
#define NPTS 8192
#define BN   (NB*NPTS)   // 32768
#define D    128
#define KNN  16
#define G    16
#define NCELLS (G*G*G)   // 4096 cells per batch
#define TPW  128         // tile slots per warp
#define NTILES (NPTS/TPW) // 64 tiles per batch
#define NW   4           // warps per query group

// ---------------- scratch (static device allocations) ----------------
__device__ float4   g_xyzw[BN];        // (-2x,-2y,-2z, |x|^2) per point (orig order)
__device__ float4   g_spts[BN];        // same, sorted by (batch, morton cell)
__device__ int      g_sidx[BN];        // sorted slot -> original local idx
__device__ unsigned g_cnt[NB*NCELLS];  // histogram
__device__ unsigned g_off[NB*NCELLS];  // cell start offsets (batch-local)
__device__ unsigned g_cur[NB*NCELLS];  // scatter cursors
__device__ unsigned g_bblo[NB*3], g_bbhi[NB*3];  // encoded bbox
__device__ float4   g_tlo[NB*NTILES];  // per-tile AABB min (xyz)
__device__ float4   g_thi[NB*NTILES];  // per-tile AABB max (xyz)
__device__ float  g_ksum[BN];          // feat . rowsum(Wk)
__device__ int    g_idx[BN*KNN];       // knn indices (within batch)
__device__ float  g_v[BN*D];           // feat @ Wv + bv
__device__ float  g_hbar[BN*D];        // sum_k attn_k * h_k
__device__ float  g_vbar[BN*D];        // sum_k attn_k * v_k
__device__ float  g_wkrs[D];           // rowsum over out-dim of Wk
__device__ float  g_wp2rs[D];          // rowsum over out-dim of Wp2
__device__ float  g_cvec[D];           // bp2 @ Wo + bo
__device__ float  g_wf[D*D];           // Wp2 @ Wo

// ---------------- helpers ----------------
__device__ __forceinline__ unsigned fenc(float f) {
    unsigned u = __float_as_uint(f);
    return (u & 0x80000000u) ? ~u : (u | 0x80000000u);
}
__device__ __forceinline__ float fdec(unsigned u) {
    return (u & 0x80000000u) ? __uint_as_float(u ^ 0x80000000u) : __uint_as_float(~u);
}
__device__ __forceinline__ unsigned msp4(unsigned x) {
    return (x & 1u) | ((x & 2u) << 2) | ((x & 4u) << 4) | ((x & 8u) << 6);
}
__device__ __forceinline__ unsigned morton3(int cx, int cy, int cz) {
    return msp4((unsigned)cx) | (msp4((unsigned)cy) << 1) | (msp4((unsigned)cz) << 2);
}
__device__ __forceinline__ int cell1(float x, float lo, float inv) {
    int v = (int)((x - lo) * inv);
    return v < 0 ? 0 : (v > G-1 ? G-1 : v);
}

// ---------------- init ----------------
__global__ void k_zero() {   // 64 blocks x 256
    int i = blockIdx.x*256 + threadIdx.x;
    g_cnt[i] = 0;
    if (i < NB*3) { g_bblo[i] = 0xFFFFFFFFu; g_bbhi[i] = 0u; }
}

// ---------------- weight prep ----------------
__global__ void k_weights(const float* __restrict__ Wk, const float* __restrict__ Wp2,
                          const float* __restrict__ bp2, const float* __restrict__ Wo,
                          const float* __restrict__ bo) {
    int i = threadIdx.x;
    float a = 0.f, b = 0.f, c = bo[i];
    for (int j = 0; j < D; ++j) { a += Wk[i*D + j]; b += Wp2[i*D + j]; }
    for (int k = 0; k < D; ++k) c = fmaf(bp2[k], Wo[k*D + i], c);
    g_wkrs[i] = a; g_wp2rs[i] = b; g_cvec[i] = c;
}

__global__ void k_wfused(const float* __restrict__ Wp2, const float* __restrict__ Wo) {
    int d = threadIdx.x & (D-1);
    int i = blockIdx.x*2 + (threadIdx.x >> 7);
    float a = 0.f;
    for (int k = 0; k < D; ++k) a = fmaf(Wp2[i*D + k], Wo[k*D + d], a);
    g_wf[i*D + d] = a;
}

// ---------------- per-point prep: xyzw + ksum ----------------
__global__ void k_prep(const float* __restrict__ xyz, const float* __restrict__ feat) {
    int warp = threadIdx.x >> 5, lane = threadIdx.x & 31;
    int p = blockIdx.x*8 + warp;
    const float* fr = feat + (size_t)p*D;
    float acc = 0.f;
    #pragma unroll
    for (int i = 0; i < 4; ++i) {
        int d = lane + 32*i;
        acc = fmaf(fr[d], g_wkrs[d], acc);
    }
    #pragma unroll
    for (int off = 16; off; off >>= 1) acc += __shfl_xor_sync(0xffffffffu, acc, off);
    if (lane == 0) {
        g_ksum[p] = acc;
        float x = xyz[3*p], y = xyz[3*p+1], z = xyz[3*p+2];
        g_xyzw[p] = make_float4(-2.f*x, -2.f*y, -2.f*z, x*x + y*y + z*z);
    }
}

// ---------------- bbox per batch (3 dims) ----------------
__global__ void k_bbox(const float* __restrict__ xyz) {   // grid (32, NB), block 256
    int b = blockIdx.y;
    __shared__ unsigned slo[3], shi[3];
    if (threadIdx.x < 3) { slo[threadIdx.x] = 0xFFFFFFFFu; shi[threadIdx.x] = 0u; }
    __syncthreads();
    int p = blockIdx.x*256 + threadIdx.x;
    if (p < NPTS) {
        const float* r = xyz + (size_t)(b*NPTS + p)*3;
        #pragma unroll
        for (int a = 0; a < 3; ++a) {
            unsigned e = fenc(r[a]);
            atomicMin(&slo[a], e); atomicMax(&shi[a], e);
        }
    }
    __syncthreads();
    if (threadIdx.x < 3) {
        atomicMin(&g_bblo[b*3 + threadIdx.x], slo[threadIdx.x]);
        atomicMax(&g_bbhi[b*3 + threadIdx.x], shi[threadIdx.x]);
    }
}

// ---------------- histogram over morton cells ----------------
__global__ void k_hist(const float* __restrict__ xyz) {
    int i = blockIdx.x*256 + threadIdx.x;
    int b = i >> 13;
    float lox = fdec(g_bblo[b*3]),   loy = fdec(g_bblo[b*3+1]), loz = fdec(g_bblo[b*3+2]);
    float ivx = (float)G/(fdec(g_bbhi[b*3])   - lox + 1e-4f);
    float ivy = (float)G/(fdec(g_bbhi[b*3+1]) - loy + 1e-4f);
    float ivz = (float)G/(fdec(g_bbhi[b*3+2]) - loz + 1e-4f);
    float x = xyz[3*i], y = xyz[3*i+1], z = xyz[3*i+2];
    unsigned m = morton3(cell1(x,lox,ivx), cell1(y,loy,ivy), cell1(z,loz,ivz));
    atomicAdd(&g_cnt[b*NCELLS + m], 1u);
}

// ---------------- exclusive scan per batch (4096 cells) ----------------
__global__ void k_scan() {   // grid NB, block 1024
    int b = blockIdx.x;
    int tid = threadIdx.x, lane = tid & 31, wid = tid >> 5;
    __shared__ unsigned ws[32];
    __shared__ unsigned carry_s;
    if (tid == 0) carry_s = 0;
    __syncthreads();
    for (int it = 0; it < NCELLS/1024; ++it) {
        unsigned carry = carry_s;
        int i = b*NCELLS + it*1024 + tid;
        unsigned v = g_cnt[i];
        unsigned s = v;
        #pragma unroll
        for (int off = 1; off < 32; off <<= 1) {
            unsigned n = __shfl_up_sync(0xffffffffu, s, off);
            if (lane >= off) s += n;
        }
        if (lane == 31) ws[wid] = s;
        __syncthreads();
        if (wid == 0) {
            unsigned t = ws[lane];
            #pragma unroll
            for (int off = 1; off < 32; off <<= 1) {
                unsigned n = __shfl_up_sync(0xffffffffu, t, off);
                if (lane >= off) t += n;
            }
            ws[lane] = t;
        }
        __syncthreads();
        unsigned excl = s - v + (wid ? ws[wid-1] : 0u) + carry;
        g_off[i] = excl; g_cur[i] = excl;
        __syncthreads();
        if (tid == 1023) carry_s = excl + v;
        __syncthreads();
    }
}

// ---------------- scatter into morton-sorted order ----------------
__global__ void k_scatter(const float* __restrict__ xyz) {
    int i = blockIdx.x*256 + threadIdx.x;
    int b = i >> 13;
    float lox = fdec(g_bblo[b*3]),   loy = fdec(g_bblo[b*3+1]), loz = fdec(g_bblo[b*3+2]);
    float ivx = (float)G/(fdec(g_bbhi[b*3])   - lox + 1e-4f);
    float ivy = (float)G/(fdec(g_bbhi[b*3+1]) - loy + 1e-4f);
    float ivz = (float)G/(fdec(g_bbhi[b*3+2]) - loz + 1e-4f);
    float x = xyz[3*i], y = xyz[3*i+1], z = xyz[3*i+2];
    unsigned m = morton3(cell1(x,lox,ivx), cell1(y,loy,ivy), cell1(z,loz,ivz));
    unsigned pos = atomicAdd(&g_cur[b*NCELLS + m], 1u);
    int slot = b*NPTS + (int)pos;
    g_spts[slot] = g_xyzw[i];
    g_sidx[slot] = i & (NPTS-1);
}

// ---------------- per-tile AABB (exact, from points) ----------------
__global__ void k_taabb() {   // 32 blocks x 256 (8 warps) ; NB*NTILES = 256 tiles
    int w = threadIdx.x >> 5, lane = threadIdx.x & 31;
    int tile = blockIdx.x*8 + w;
    float xmn = CUDART_INF_F, ymn = CUDART_INF_F, zmn = CUDART_INF_F;
    float xmx = -CUDART_INF_F, ymx = -CUDART_INF_F, zmx = -CUDART_INF_F;
    #pragma unroll
    for (int i = 0; i < TPW/32; ++i) {
        float4 c = g_spts[tile*TPW + lane + i*32];
        float x = -0.5f*c.x, y = -0.5f*c.y, z = -0.5f*c.z;
        xmn = fminf(xmn, x); xmx = fmaxf(xmx, x);
        ymn = fminf(ymn, y); ymx = fmaxf(ymx, y);
        zmn = fminf(zmn, z); zmx = fmaxf(zmx, z);
    }
    #pragma unroll
    for (int off = 16; off; off >>= 1) {
        xmn = fminf(xmn, __shfl_xor_sync(0xffffffffu, xmn, off));
        xmx = fmaxf(xmx, __shfl_xor_sync(0xffffffffu, xmx, off));
        ymn = fminf(ymn, __shfl_xor_sync(0xffffffffu, ymn, off));
        ymx = fmaxf(ymx, __shfl_xor_sync(0xffffffffu, ymx, off));
        zmn = fminf(zmn, __shfl_xor_sync(0xffffffffu, zmn, off));
        zmx = fmaxf(zmx, __shfl_xor_sync(0xffffffffu, zmx, off));
    }
    if (lane == 0) {
        g_tlo[tile] = make_float4(xmn, ymn, zmn, 0.f);
        g_thi[tile] = make_float4(xmx, ymx, zmx, 0.f);
    }
}

// ---------------- kNN: AABB-pruned tile scan, 4 warps/group ----------------
__global__ void __launch_bounds__(128) k_knn() {
    __shared__ float4 tile_s[NW][TPW];     // 8KB
    __shared__ float  sth[NW][32];         // per-(warp,query) 16th-dist^2
    __shared__ float  md[KNN*NW*32];       // merge keys
    __shared__ int    mi[KNN*NW*32];       // merge slot ids

    int w = threadIdx.x >> 5, lane = threadIdx.x & 31;
    int qslot0 = blockIdx.x*32;            // 32 consecutive morton-sorted queries
    int b = qslot0 >> 13, bbase = b*NPTS;
    int ql = qslot0 & (NPTS-1);
    int slot = qslot0 + lane;
    float4 qc = g_spts[slot];
    float qx = -0.5f*qc.x, qy = -0.5f*qc.y, qz = -0.5f*qc.z, qw = qc.w;

    volatile float* sv = &sth[0][0];
    sth[w][lane] = CUDART_INF_F;

    float kk[KNN]; int ii[KNN];
    #pragma unroll
    for (int s = 0; s < KNN; ++s) { kk[s] = CUDART_INF_F; ii[s] = 0; }
    float pkey = 0.f; int psl = 0; bool pval = false;

#define KNN_FLUSH() do {                                              \
        float ck = pkey; int ci = psl;                                \
        _Pragma("unroll")                                             \
        for (int s = 0; s < KNN; ++s) {                               \
            bool sw = ck < kk[s];                                     \
            float tk = kk[s]; int ti = ii[s];                         \
            kk[s] = sw ? ck : tk;  ii[s] = sw ? ci : ti;              \
            ck = sw ? tk : ck;     ci = sw ? ti : ci;                 \
        }                                                             \
    } while (0)

#define SCAN_TILE(T0, CAP) do {                                       \
        __syncwarp();                                                 \
        _Pragma("unroll")                                             \
        for (int i_ = 0; i_ < TPW/32; ++i_)                           \
            tile_s[w][lane + i_*32] = g_spts[bbase + (T0) + lane + i_*32]; \
        __syncwarp();                                                 \
        float thr = fminf(kk[KNN-1], (CAP));                          \
        _Pragma("unroll 8")                                           \
        for (int j_ = 0; j_ < TPW; ++j_) {                            \
            float4 c = tile_s[w][j_];                                 \
            float key = fmaf(c.x, qx, fmaf(c.y, qy, fmaf(c.z, qz, c.w))); \
            bool hit = key < thr;                                     \
            if (__any_sync(0xffffffffu, hit && pval)) {               \
                if (pval) { KNN_FLUSH(); thr = fminf(kk[KNN-1], (CAP)); } \
                pval = false;                                         \
            }                                                         \
            if (hit) { pkey = key; psl = (T0) + j_; pval = true; }    \
        }                                                             \
        if (__any_sync(0xffffffffu, pval)) {                          \
            if (pval) KNN_FLUSH();                                    \
            pval = false;                                             \
        }                                                             \
        sth[w][lane] = kk[KNN-1] + qw;                                \
    } while (0)

    __syncthreads();
    int tq = ql >> 7;                       // own tile (holds all 32 queries)
    if (w == 0) SCAN_TILE(tq*TPW, CUDART_INF_F);   // warm-start: compact 3D blob
    __syncthreads();

    // each warp handles 16 of the 64 tiles, pruned by exact point-AABB distance
    for (int t = w; t < NTILES; t += NW) {
        if (t == tq) continue;
        float d2s = fminf(fminf(sv[lane], sv[32+lane]), fminf(sv[64+lane], sv[96+lane]));
        d2s = fminf(d2s, kk[KNN-1] + qw);
        float4 blo = g_tlo[b*NTILES + t];
        float4 bhi = g_thi[b*NTILES + t];
        float dx = fmaxf(fmaxf(blo.x - qx, qx - bhi.x), 0.f);
        float dy = fmaxf(fmaxf(blo.y - qy, qy - bhi.y), 0.f);
        float dz = fmaxf(fmaxf(blo.z - qz, qz - bhi.z), 0.f);
        float cd2 = fmaf(dx, dx, fmaf(dy, dy, dz*dz));
        if (__all_sync(0xffffffffu, cd2 >= d2s + 1e-4f)) continue;  // margin > key rounding
        SCAN_TILE(t*TPW, d2s - qw);
    }
#undef SCAN_TILE
#undef KNN_FLUSH

    // ---- 4-way merge of sorted 16-lists (disjoint tiles -> no duplicates) ----
    #pragma unroll
    for (int s = 0; s < KNN; ++s) {
        md[s*(NW*32) + w*32 + lane] = kk[s];
        mi[s*(NW*32) + w*32 + lane] = ii[s];
    }
    __syncthreads();
    if (w == 0) {
        int p0 = 0, p1 = 0, p2 = 0, p3 = 0;
        int oq = g_sidx[slot];
        int* op = g_idx + (size_t)(bbase + oq)*KNN;
        #pragma unroll
        for (int s = 0; s < KNN; ++s) {
            float h0 = md[p0*128 +  0 + lane];
            float h1 = md[p1*128 + 32 + lane];
            float h2 = md[p2*128 + 64 + lane];
            float h3 = md[p3*128 + 96 + lane];
            float best = h0; int bw = 0;
            if (h1 < best) { best = h1; bw = 1; }
            if (h2 < best) { best = h2; bw = 2; }
            if (h3 < best) { best = h3; bw = 3; }
            int pj = (bw == 0) ? p0 : (bw == 1) ? p1 : (bw == 2) ? p2 : p3;
            int sl = mi[pj*128 + bw*32 + lane];
            op[s] = g_sidx[bbase + sl];
            if (bw == 0) ++p0; else if (bw == 1) ++p1; else if (bw == 2) ++p2; else ++p3;
        }
    }
}

// ---------------- v = feat @ Wv + bv ----------------
__global__ void k_gemm_v(const float* __restrict__ feat, const float* __restrict__ Wv,
                         const float* __restrict__ bv) {
    __shared__ float As[16][132];
    __shared__ float Ws[16][132];
    int m0 = blockIdx.x*128;
    int tx = threadIdx.x & 15, ty = threadIdx.x >> 4;
    float acc[8][8];
    #pragma unroll
    for (int i = 0; i < 8; ++i)
        #pragma unroll
        for (int j = 0; j < 8; ++j) acc[i][j] = 0.f;

    for (int kc = 0; kc < D; kc += 16) {
        __syncthreads();
        { int c = threadIdx.x & 3, r = threadIdx.x >> 2;
          #pragma unroll
          for (int rr = 0; rr < 2; ++rr) {
              int mm = r + rr*64;
              float4 v = *(const float4*)&feat[(size_t)(m0+mm)*D + kc + c*4];
              As[c*4+0][mm] = v.x; As[c*4+1][mm] = v.y;
              As[c*4+2][mm] = v.z; As[c*4+3][mm] = v.w;
          }
        }
        { int k = threadIdx.x >> 5, c4 = threadIdx.x & 31;
          #pragma unroll
          for (int kk = 0; kk < 2; ++kk) {
              float4 v = *(const float4*)&Wv[(size_t)(kc + k + kk*8)*D + c4*4];
              Ws[k + kk*8][c4*4+0] = v.x; Ws[k + kk*8][c4*4+1] = v.y;
              Ws[k + kk*8][c4*4+2] = v.z; Ws[k + kk*8][c4*4+3] = v.w;
          }
        }
        __syncthreads();
        #pragma unroll
        for (int k = 0; k < 16; ++k) {
            float a[8], bb[8];
            #pragma unroll
            for (int i = 0; i < 8; ++i) a[i]  = As[k][ty*8 + i];
            #pragma unroll
            for (int j = 0; j < 8; ++j) bb[j] = Ws[k][tx*8 + j];
            #pragma unroll
            for (int i = 0; i < 8; ++i)
                #pragma unroll
                for (int j = 0; j < 8; ++j) acc[i][j] = fmaf(a[i], bb[j], acc[i][j]);
        }
    }
    #pragma unroll
    for (int i = 0; i < 8; ++i) {
        int m = m0 + ty*8 + i;
        #pragma unroll
        for (int j = 0; j < 8; ++j) acc[i][j] += bv[tx*8 + j];
        *(float4*)&g_v[(size_t)m*D + tx*8]     = make_float4(acc[i][0], acc[i][1], acc[i][2], acc[i][3]);
        *(float4*)&g_v[(size_t)m*D + tx*8 + 4] = make_float4(acc[i][4], acc[i][5], acc[i][6], acc[i][7]);
    }
}

// ---------------- fused attention (warp per point) ----------------
__global__ void k_fuse(const float* __restrict__ xyz, const float* __restrict__ Wp1,
                       const float* __restrict__ bp1) {
    __shared__ float sw0[D], sw1[D], sw2[D], sb1[D], srs[D];
    int tid = threadIdx.x;
    sw0[tid] = Wp1[tid]; sw1[tid] = Wp1[D + tid]; sw2[tid] = Wp1[2*D + tid];
    sb1[tid] = bp1[tid]; srs[tid] = g_wp2rs[tid];
    __syncthreads();

    int warp = tid >> 5, lane = tid & 31;
    int p = blockIdx.x*4 + warp;
    int bbase = p & ~(NPTS-1);

    float w0[4], w1[4], w2[4], b1r[4], rs[4];
    #pragma unroll
    for (int i = 0; i < 4; ++i) {
        int d = lane + 32*i;
        w0[i] = sw0[d]; w1[i] = sw1[d]; w2[i] = sw2[d]; b1r[i] = sb1[d]; rs[i] = srs[d];
    }

    float rx = 0.f, ry = 0.f, rz = 0.f, ks = 0.f; int row = 0;
    if (lane < KNN) {
        int nb = g_idx[(size_t)p*KNN + lane];
        row = bbase + nb;
        float qx = xyz[3*p], qy = xyz[3*p+1], qz = xyz[3*p+2];
        rx = qx - xyz[3*row]; ry = qy - xyz[3*row+1]; rz = qz - xyz[3*row+2];
        ks = g_ksum[row];
    }

    float mysc = -CUDART_INF_F;
    #pragma unroll
    for (int k = 0; k < KNN; ++k) {
        float bx = __shfl_sync(0xffffffffu, rx, k);
        float by = __shfl_sync(0xffffffffu, ry, k);
        float bz = __shfl_sync(0xffffffffu, rz, k);
        float part = 0.f;
        #pragma unroll
        for (int i = 0; i < 4; ++i) {
            float h = fmaf(bx, w0[i], fmaf(by, w1[i], fmaf(bz, w2[i], b1r[i])));
            h = fmaxf(h, 0.f);
            part = fmaf(h, rs[i], part);
        }
        #pragma unroll
        for (int off = 16; off; off >>= 1) part += __shfl_xor_sync(0xffffffffu, part, off);
        if (lane == k) mysc = part - ks;
    }
    float mx = mysc;
    #pragma unroll
    for (int off = 16; off; off >>= 1) mx = fmaxf(mx, __shfl_xor_sync(0xffffffffu, mx, off));
    float e = (lane < KNN) ? __expf(mysc - mx) : 0.f;
    float ssum = e;
    #pragma unroll
    for (int off = 16; off; off >>= 1) ssum += __shfl_xor_sync(0xffffffffu, ssum, off);
    float attn = e / ssum;

    float hb[4] = {0,0,0,0}, vb[4] = {0,0,0,0};
    #pragma unroll
    for (int k = 0; k < KNN; ++k) {
        float a  = __shfl_sync(0xffffffffu, attn, k);
        float bx = __shfl_sync(0xffffffffu, rx, k);
        float by = __shfl_sync(0xffffffffu, ry, k);
        float bz = __shfl_sync(0xffffffffu, rz, k);
        int   r  = __shfl_sync(0xffffffffu, row, k);
        const float* vr = g_v + (size_t)r*D;
        #pragma unroll
        for (int i = 0; i < 4; ++i) {
            int d = lane + 32*i;
            float h = fmaf(bx, w0[i], fmaf(by, w1[i], fmaf(bz, w2[i], b1r[i])));
            h = fmaxf(h, 0.f);
            hb[i] = fmaf(a, h, hb[i]);
            vb[i] = fmaf(a, vr[d], vb[i]);
        }
    }
    #pragma unroll
    for (int i = 0; i < 4; ++i) {
        int d = lane + 32*i;
        g_hbar[(size_t)p*D + d] = hb[i];
        g_vbar[(size_t)p*D + d] = vb[i];
    }
}

// ---------------- out = feat + gamma*(vbar@Wo + hbar@Wf + cvec) ----------------
__global__ void k_out(const float* __restrict__ feat, const float* __restrict__ Wo,
                      const float* __restrict__ gamma, float* __restrict__ out) {
    __shared__ float As[16][132];
    __shared__ float Ws[16][132];
    int m0 = blockIdx.x*128;
    int tx = threadIdx.x & 15, ty = threadIdx.x >> 4;
    float acc[8][8];
    #pragma unroll
    for (int i = 0; i < 8; ++i)
        #pragma unroll
        for (int j = 0; j < 8; ++j) acc[i][j] = 0.f;

    for (int ph = 0; ph < 2; ++ph) {
        const float* A = ph ? g_hbar : g_vbar;
        const float* W = ph ? g_wf   : Wo;
        for (int kc = 0; kc < D; kc += 16) {
            __syncthreads();
            { int c = threadIdx.x & 3, r = threadIdx.x >> 2;
              #pragma unroll
              for (int rr = 0; rr < 2; ++rr) {
                  int mm = r + rr*64;
                  float4 v = *(const float4*)&A[(size_t)(m0+mm)*D + kc + c*4];
                  As[c*4+0][mm] = v.x; As[c*4+1][mm] = v.y;
                  As[c*4+2][mm] = v.z; As[c*4+3][mm] = v.w;
              }
            }
            { int k = threadIdx.x >> 5, c4 = threadIdx.x & 31;
              #pragma unroll
              for (int kk = 0; kk < 2; ++kk) {
                  float4 v = *(const float4*)&W[(size_t)(kc + k + kk*8)*D + c4*4];
                  Ws[k + kk*8][c4*4+0] = v.x; Ws[k + kk*8][c4*4+1] = v.y;
                  Ws[k + kk*8][c4*4+2] = v.z; Ws[k + kk*8][c4*4+3] = v.w;
              }
            }
            __syncthreads();
            #pragma unroll
            for (int k = 0; k < 16; ++k) {
                float a[8], bb[8];
                #pragma unroll
                for (int i = 0; i < 8; ++i) a[i]  = As[k][ty*8 + i];
                #pragma unroll
                for (int j = 0; j < 8; ++j) bb[j] = Ws[k][tx*8 + j];
                #pragma unroll
                for (int i = 0; i < 8; ++i)
                    #pragma unroll
                    for (int j = 0; j < 8; ++j) acc[i][j] = fmaf(a[i], bb[j], acc[i][j]);
            }
        }
    }
    float g = *gamma;
    float cv[8];
    #pragma unroll
    for (int j = 0; j < 8; ++j) cv[j] = g_cvec[tx*8 + j];
    #pragma unroll
    for (int i = 0; i < 8; ++i) {
        int m = m0 + ty*8 + i;
        float4 f0 = *(const float4*)&feat[(size_t)m*D + tx*8];
        float4 f1 = *(const float4*)&feat[(size_t)m*D + tx*8 + 4];
        float o0 = f0.x + g*(acc[i][0] + cv[0]);
        float o1 = f0.y + g*(acc[i][1] + cv[1]);
        float o2 = f0.z + g*(acc[i][2] + cv[2]);
        float o3 = f0.w + g*(acc[i][3] + cv[3]);
        float o4 = f1.x + g*(acc[i][4] + cv[4]);
        float o5 = f1.y + g*(acc[i][5] + cv[5]);
        float o6 = f1.z + g*(acc[i][6] + cv[6]);
        float o7 = f1.w + g*(acc[i][7] + cv[7]);
        *(float4*)&out[(size_t)m*D + tx*8]     = make_float4(o0, o1, o2, o3);
        *(float4*)&out[(size_t)m*D + tx*8 + 4] = make_float4(o4, o5, o6, o7);
    }
}

// ---------------- launch ----------------
extern "C" void kernel_launch(void* const* d_in, const int* in_sizes, int n_in,
                              void* d_out, int out_size) {
    const float* xyz  = (const float*)d_in[0];
    const float* feat = (const float*)d_in[1];
    // d_in[2]=Wq, d_in[3]=bq, d_in[5]=bk : mathematically cancel in softmax, unused
    const float* Wk   = (const float*)d_in[4];
    const float* Wv   = (const float*)d_in[6];
    const float* bv   = (const float*)d_in[7];
    const float* Wp1  = (const float*)d_in[8];
    const float* bp1  = (const float*)d_in[9];
    const float* Wp2  = (const float*)d_in[10];
    const float* bp2  = (const float*)d_in[11];
    const float* Wo   = (const float*)d_in[12];
    const float* bo   = (const float*)d_in[13];
    const float* gmm  = (const float*)d_in[14];
    float* out = (float*)d_out;

    k_zero<<<NB*NCELLS/256, 256>>>();
    k_weights<<<1, 128>>>(Wk, Wp2, bp2, Wo, bo);
    k_wfused<<<64, 256>>>(Wp2, Wo);
    k_prep<<<BN/8, 256>>>(xyz, feat);
    k_bbox<<<dim3(32, NB), 256>>>(xyz);
    k_hist<<<BN/256, 256>>>(xyz);
    k_scan<<<NB, 1024>>>();
    k_scatter<<<BN/256, 256>>>(xyz);
    k_taabb<<<NB*NTILES/8, 256>>>();
    k_knn<<<BN/32, 128>>>();
    k_gemm_v<<<BN/128, 256>>>(feat, Wv, bv);
    k_fuse<<<BN/4, 128>>>(xyz, Wp1, bp1);
    k_out<<<BN/128, 256>>>(feat, Wo, gmm, out);
}